// round 6
// baseline (speedup 1.0000x reference)
#include <cuda_runtime.h>
#include <cuda_fp16.h>
#include <stdint.h>
#include <math.h>

#define NN 50000
#define EC 800000
#define EETOT 850000
#define CF 256

// ---------------- scratch (static __device__, no allocations) ----------------
// A operand packed as half2 k-pairs: word w of row r = {v[2w], v[2w+1]}
__device__ __align__(256) uint32_t g_ahi[NN * 128];
__device__ __align__(256) uint32_t g_alo[NN * 128];
// W packed by k-pairs across n: word [p][n] = {W[2p][n], W[2p+1][n]}
__device__ __align__(256) uint32_t g_w1h[128 * 256];
__device__ __align__(256) uint32_t g_w1l[128 * 256];
__device__ __align__(256) uint32_t g_w2h[128 * 256];
__device__ __align__(256) uint32_t g_w2l[128 * 256];
__device__ __align__(256) float g_h[NN * CF];        // GEMM output fp32 (alpha reads this)
__device__ __align__(256) uint32_t g_hf16[NN * 128]; // GEMM output packed half2 (agg gathers this)
__device__ __align__(256) float g_asrc[NN * 4];
__device__ __align__(256) float g_adst[NN * 4];
__device__ int g_rowptr[NN + 1];
__device__ int g_cnt[NN];
__device__ int g_cur[NN];
__device__ int g_colsrc[EETOT];
__device__ int g_is64;   // 1 if edge_index buffer is int64, 0 if int32

// ---------------- helpers ----------------
__device__ __forceinline__ uint32_t pack_split_h2(float v0, float v1, uint32_t& lo_out) {
    __half h0 = __float2half_rn(v0);
    __half l0 = __float2half_rn(v0 - __half2float(h0));
    __half h1 = __float2half_rn(v1);
    __half l1 = __float2half_rn(v1 - __half2float(h1));
    __half2 hh = __halves2half2(h0, h1);
    __half2 ll = __halves2half2(l0, l1);
    lo_out = *reinterpret_cast<uint32_t*>(&ll);
    return *reinterpret_cast<uint32_t*>(&hh);
}

#define MMA_F16(c, a, b0, b1)                                                          \
    asm volatile(                                                                      \
        "mma.sync.aligned.m16n8k16.row.col.f32.f16.f16.f32 "                           \
        "{%0,%1,%2,%3},{%4,%5,%6,%7},{%8,%9},{%0,%1,%2,%3};"                           \
        : "+f"(c[0]), "+f"(c[1]), "+f"(c[2]), "+f"(c[3])                               \
        : "r"(a[0]), "r"(a[1]), "r"(a[2]), "r"(a[3]), "r"(b0), "r"(b1))

// Read logical edge_index element `pos` regardless of storage dtype; clamp to valid.
__device__ __forceinline__ int edge_at(const int* __restrict__ ei32, long pos, int is64) {
    int v = is64 ? ei32[2 * pos] : ei32[pos];
    v = (v < 0) ? 0 : v;
    return (v >= NN) ? (NN - 1) : v;
}

// ---------------- edge dtype detection ----------------
__global__ void detect_kernel(const int* __restrict__ ei32) {
    if (threadIdx.x == 0) {
        int all0 = 1;
        for (int k = 1; k < 129; k += 2)
            if (ei32[k] != 0) { all0 = 0; break; }
        g_is64 = all0;
    }
}

// ---------------- pre-pass: fp16 hi/lo split, packed half2 ----------------
__global__ void split_x_kernel(const float* __restrict__ x) {
    int i = blockIdx.x * 256 + threadIdx.x;
    if (i >= NN * 128) return;
    float v0 = x[2 * i], v1 = x[2 * i + 1];
    uint32_t lo;
    uint32_t hi = pack_split_h2(v0, v1, lo);
    g_ahi[i] = hi;
    g_alo[i] = lo;
}

template <int L>
__global__ void split_w_kernel(const float* __restrict__ W) {
    uint32_t* wh = (L == 0) ? g_w1h : g_w2h;
    uint32_t* wl = (L == 0) ? g_w1l : g_w2l;
    int i = blockIdx.x * 256 + threadIdx.x;
    if (i >= 128 * 256) return;
    int p = i >> 8, n = i & 255;
    float v0 = W[(2 * p) * 256 + n], v1 = W[(2 * p + 1) * 256 + n];
    uint32_t lo;
    uint32_t hi = pack_split_h2(v0, v1, lo);
    wh[i] = hi;
    wl[i] = lo;
}

// ---------------- CSR build ----------------
__global__ void zero_kernel() {
    int i = blockIdx.x * 256 + threadIdx.x;
    if (i < NN) { g_cnt[i] = 0; g_cur[i] = 0; }
}

__global__ void hist_kernel(const int* __restrict__ ei32) {
    int i = blockIdx.x * 256 + threadIdx.x;
    if (i >= EETOT) return;
    int is64 = g_is64;
    int dst = (i < EC) ? edge_at(ei32, (long)EC + i, is64) : (i - EC);
    atomicAdd(&g_cnt[dst], 1);
}

__global__ void scan_kernel() {
    __shared__ int s[1024];
    int t = threadIdx.x;
    const int chunk = (NN + 1023) / 1024;
    int lo = t * chunk;
    int hi = lo + chunk; if (hi > NN) hi = NN;
    int sum = 0;
    for (int i = lo; i < hi; i++) sum += g_cnt[i];
    s[t] = sum;
    __syncthreads();
    for (int d = 1; d < 1024; d <<= 1) {
        int v = (t >= d) ? s[t - d] : 0;
        __syncthreads();
        s[t] += v;
        __syncthreads();
    }
    int run = s[t] - sum;
    for (int i = lo; i < hi; i++) { g_rowptr[i] = run; run += g_cnt[i]; }
    if (t == 0) g_rowptr[NN] = EETOT;
}

__global__ void scatter_kernel(const int* __restrict__ ei32) {
    int i = blockIdx.x * 256 + threadIdx.x;
    if (i >= EETOT) return;
    int is64 = g_is64;
    int src, dst;
    if (i < EC) {
        src = edge_at(ei32, i, is64);
        dst = edge_at(ei32, (long)EC + i, is64);
    } else {
        src = i - EC;
        dst = i - EC;
    }
    int pos = g_rowptr[dst] + atomicAdd(&g_cur[dst], 1);
    g_colsrc[pos] = src;
}

// ---------------- GEMM: g_h[M,256] = A[M,256] @ W[256,256], split-FP16 (3 products) ----------------
// CTA tile 128x128, BK=16 (one m16n8k16 step), 8 warps (2x4), warp tile 64x32.
// Double-buffered static smem, 1 __syncthreads per K-tile.
// Epilogue stores fp32 (for alpha) + packed half2 (for the agg gather).
template <int LAYER>
__global__ void __launch_bounds__(256) gemmf16_kernel(int M) {
    const uint32_t* __restrict__ Ah = g_ahi;
    const uint32_t* __restrict__ Al = g_alo;
    const uint32_t* __restrict__ Bh = (LAYER == 0) ? g_w1h : g_w2h;
    const uint32_t* __restrict__ Bl = (LAYER == 0) ? g_w1l : g_w2l;
    float* __restrict__ Co = g_h;

    __shared__ __align__(16) uint32_t sAh[2][128 * 12];
    __shared__ __align__(16) uint32_t sAl[2][128 * 12];
    __shared__ __align__(16) uint32_t sBh[2][8 * 136];
    __shared__ __align__(16) uint32_t sBl[2][8 * 136];

    int tid = threadIdx.x;
    int lane = tid & 31, warp = tid >> 5;
    int g = lane >> 2, t4 = lane & 3;
    int wm = (warp >> 2) * 64, wn = (warp & 3) * 32;
    int bm = blockIdx.x * 128, bn = blockIdx.y * 128;

    float acc[4][4][4] = {};

    int arow = tid >> 1, aw = (tid & 1) * 4;
    int brow = tid >> 5, bw = (tid & 31) * 4;
    int agrow = bm + arow; if (agrow > M - 1) agrow = M - 1;  // clamp; OOB rows never stored

    uint4 rAh, rAl, rBh, rBl;
    auto gload = [&](int k0) {
        int p = k0 >> 1;
        long ga = (long)agrow * 128 + p + aw;
        rAh = *(const uint4*)(Ah + ga);
        rAl = *(const uint4*)(Al + ga);
        long gb = (long)(p + brow) * 256 + bn + bw;
        rBh = *(const uint4*)(Bh + gb);
        rBl = *(const uint4*)(Bl + gb);
    };
    auto sstore = [&](int st) {
        *(uint4*)&sAh[st][arow * 12 + aw] = rAh;
        *(uint4*)&sAl[st][arow * 12 + aw] = rAl;
        *(uint4*)&sBh[st][brow * 136 + bw] = rBh;
        *(uint4*)&sBl[st][brow * 136 + bw] = rBl;
    };

    gload(0);
    sstore(0);
    __syncthreads();

#pragma unroll 1
    for (int it = 0; it < 16; it++) {
        int cb = it & 1;
        if (it < 15) gload((it + 1) * 16);
        uint32_t ah[4][4], al[4][4];
#pragma unroll
        for (int mi = 0; mi < 4; mi++) {
            int r0 = wm + mi * 16 + g;
            ah[mi][0] = sAh[cb][r0 * 12 + t4];
            ah[mi][1] = sAh[cb][(r0 + 8) * 12 + t4];
            ah[mi][2] = sAh[cb][r0 * 12 + 4 + t4];
            ah[mi][3] = sAh[cb][(r0 + 8) * 12 + 4 + t4];
            al[mi][0] = sAl[cb][r0 * 12 + t4];
            al[mi][1] = sAl[cb][(r0 + 8) * 12 + t4];
            al[mi][2] = sAl[cb][r0 * 12 + 4 + t4];
            al[mi][3] = sAl[cb][(r0 + 8) * 12 + 4 + t4];
        }
#pragma unroll
        for (int ni = 0; ni < 4; ni++) {
            int cidx = wn + ni * 8 + g;
            uint32_t bh0 = sBh[cb][t4 * 136 + cidx];
            uint32_t bh1 = sBh[cb][(4 + t4) * 136 + cidx];
            uint32_t bl0 = sBl[cb][t4 * 136 + cidx];
            uint32_t bl1 = sBl[cb][(4 + t4) * 136 + cidx];
#pragma unroll
            for (int mi = 0; mi < 4; mi++) {
                MMA_F16(acc[mi][ni], ah[mi], bh0, bh1);
                MMA_F16(acc[mi][ni], ah[mi], bl0, bl1);
                MMA_F16(acc[mi][ni], al[mi], bh0, bh1);
            }
        }
        if (it < 15) {
            sstore(cb ^ 1);
            __syncthreads();
        }
    }

#pragma unroll
    for (int mi = 0; mi < 4; mi++)
#pragma unroll
        for (int ni = 0; ni < 4; ni++) {
            int r = bm + wm + mi * 16 + g;
            int cc = bn + wn + ni * 8 + 2 * t4;     // even channel index
            int wd = cc >> 1;                        // half2 word index
            if (r < M) {
                *(float2*)&Co[(long)r * 256 + cc] = make_float2(acc[mi][ni][0], acc[mi][ni][1]);
                __half2 p = __floats2half2_rn(acc[mi][ni][0], acc[mi][ni][1]);
                g_hf16[(long)r * 128 + wd] = *reinterpret_cast<uint32_t*>(&p);
            }
            if (r + 8 < M) {
                *(float2*)&Co[(long)(r + 8) * 256 + cc] = make_float2(acc[mi][ni][2], acc[mi][ni][3]);
                __half2 p = __floats2half2_rn(acc[mi][ni][2], acc[mi][ni][3]);
                g_hf16[(long)(r + 8) * 128 + wd] = *reinterpret_cast<uint32_t*>(&p);
            }
        }
}

// ---------------- alpha_src / alpha_dst: warp per node, reads fp32 g_h ----------------
template <int H, int CH>
__global__ void alpha_kernel(const float* __restrict__ a_s, const float* __restrict__ a_d) {
    int node = blockIdx.x * 8 + (threadIdx.x >> 5);
    if (node >= NN) return;
    int lane = threadIdx.x & 31;
    const float4* hv = (const float4*)(g_h + (long)node * CF) + lane * 2;
    float4 h0 = hv[0], h1 = hv[1];
    const float4* sv = (const float4*)a_s + lane * 2;
    const float4* dv = (const float4*)a_d + lane * 2;
    float4 s0 = sv[0], s1 = sv[1], d0 = dv[0], d1 = dv[1];
    float ps = h0.x * s0.x + h0.y * s0.y + h0.z * s0.z + h0.w * s0.w +
               h1.x * s1.x + h1.y * s1.y + h1.z * s1.z + h1.w * s1.w;
    float pd = h0.x * d0.x + h0.y * d0.y + h0.z * d0.z + h0.w * d0.w +
               h1.x * d1.x + h1.y * d1.y + h1.z * d1.z + h1.w * d1.w;
    const int GS = CH / 8;
#pragma unroll
    for (int m = 1; m < GS; m <<= 1) {
        ps += __shfl_xor_sync(0xffffffffu, ps, m);
        pd += __shfl_xor_sync(0xffffffffu, pd, m);
    }
    if ((lane & (GS - 1)) == 0) {
        int head = lane / GS;
        g_asrc[node * H + head] = ps;
        g_adst[node * H + head] = pd;
    }
}

// ---------------- fused softmax-attention aggregation: warp per dst node ----------------
// Gathers packed-half2 features (16 B/lane/edge); accumulates in fp32.
// SPLIT path writes elu(result) fp16-split packed into g_ahi/g_alo (feeds next GEMM).
template <int H, int CH, bool ELU_ACT, bool SPLIT>
__global__ void agg_kernel(const float* __restrict__ bias, float* __restrict__ out) {
    int node = blockIdx.x * 8 + (threadIdx.x >> 5);
    if (node >= NN) return;
    int lane = threadIdx.x & 31;
    int head = (lane * 8) / CH;
    float ad = g_adst[node * H + head];
    const uint4* hb = (const uint4*)g_hf16;   // 32 uint4 per node row
    float a0 = 0, a1 = 0, a2 = 0, a3 = 0, a4 = 0, a5 = 0, a6 = 0, a7 = 0;
    float denom = 0.f;
    int j0 = g_rowptr[node], j1 = g_rowptr[node + 1];
    int src_next = (j0 < j1) ? __ldg(&g_colsrc[j0]) : 0;
    for (int j = j0; j < j1; j++) {
        int src = src_next;
        if (j + 1 < j1) src_next = __ldg(&g_colsrc[j + 1]);
        float e = __ldg(&g_asrc[src * H + head]) + ad;
        e = (e > 0.f) ? e : 0.2f * e;
        float w = __expf(e);
        denom += w;
        uint4 pk = __ldg(&hb[(long)src * 32 + lane]);  // 8 halfs = channels lane*8..lane*8+7
        float2 f0 = __half22float2(*reinterpret_cast<__half2*>(&pk.x));
        float2 f1 = __half22float2(*reinterpret_cast<__half2*>(&pk.y));
        float2 f2 = __half22float2(*reinterpret_cast<__half2*>(&pk.z));
        float2 f3 = __half22float2(*reinterpret_cast<__half2*>(&pk.w));
        a0 += w * f0.x; a1 += w * f0.y; a2 += w * f1.x; a3 += w * f1.y;
        a4 += w * f2.x; a5 += w * f2.y; a6 += w * f3.x; a7 += w * f3.y;
    }
    float inv = 1.f / denom;
    const float4* bb = (const float4*)bias + lane * 2;
    float4 b0 = bb[0], b1 = bb[1];
    float r[8];
    r[0] = a0 * inv + b0.x; r[1] = a1 * inv + b0.y;
    r[2] = a2 * inv + b0.z; r[3] = a3 * inv + b0.w;
    r[4] = a4 * inv + b1.x; r[5] = a5 * inv + b1.y;
    r[6] = a6 * inv + b1.z; r[7] = a7 * inv + b1.w;
    if (ELU_ACT) {
#pragma unroll
        for (int k = 0; k < 8; k++) r[k] = (r[k] > 0.f) ? r[k] : expm1f(r[k]);
    }
    if (SPLIT) {
        uint32_t wh[4], wl[4];
#pragma unroll
        for (int p = 0; p < 4; p++) wh[p] = pack_split_h2(r[2 * p], r[2 * p + 1], wl[p]);
        long ob = (long)node * 128 + lane * 4;
        *(uint4*)&g_ahi[ob] = *(uint4*)wh;
        *(uint4*)&g_alo[ob] = *(uint4*)wl;
    } else {
        long ob = (long)node * CF + lane * 8;
        *(float4*)&out[ob]     = make_float4(r[0], r[1], r[2], r[3]);
        *(float4*)&out[ob + 4] = make_float4(r[4], r[5], r[6], r[7]);
    }
}

// ---------------- launch: kernel launches ONLY (graph-capture safe) ----------------
extern "C" void kernel_launch(void* const* d_in, const int* in_sizes, int n_in,
                              void* d_out, int out_size) {
    const float* x    = (const float*)d_in[0];
    const int* ei32   = (const int*)d_in[1];   // int32 OR int64 storage; detected on device
    const float* W1   = (const float*)d_in[2];
    const float* as1  = (const float*)d_in[3];
    const float* ad1  = (const float*)d_in[4];
    const float* b1   = (const float*)d_in[5];
    const float* W2   = (const float*)d_in[6];
    const float* as2  = (const float*)d_in[7];
    const float* ad2  = (const float*)d_in[8];
    const float* b2   = (const float*)d_in[9];
    float* out        = (float*)d_out;

    detect_kernel<<<1, 32>>>(ei32);

    split_x_kernel<<<(NN * 128 + 255) / 256, 256>>>(x);
    split_w_kernel<0><<<(128 * 256 + 255) / 256, 256>>>(W1);
    split_w_kernel<1><<<(128 * 256 + 255) / 256, 256>>>(W2);

    zero_kernel<<<(NN + 255) / 256, 256>>>();
    hist_kernel<<<(EETOT + 255) / 256, 256>>>(ei32);
    scan_kernel<<<1, 1024>>>();
    scatter_kernel<<<(EETOT + 255) / 256, 256>>>(ei32);

    dim3 gg((NN + 127) / 128, 2);
    // ---- layer 1: GATConv(256, 64, heads=4) + ELU ----
    gemmf16_kernel<0><<<gg, 256>>>(NN);
    alpha_kernel<4, 64><<<(NN + 7) / 8, 256>>>(as1, ad1);
    agg_kernel<4, 64, true, true><<<(NN + 7) / 8, 256>>>(b1, (float*)0);
    // ---- layer 2: GATConv(256, 256, heads=1) ----
    gemmf16_kernel<1><<<gg, 256>>>(NN);
    alpha_kernel<1, 256><<<(NN + 7) / 8, 256>>>(as2, ad2);
    agg_kernel<1, 256, false, false><<<(NN + 7) / 8, 256>>>(b2, out);
}

// round 7
// speedup vs baseline: 1.1071x; 1.1071x over previous
#include <cuda_runtime.h>
#include <cuda_fp16.h>
#include <stdint.h>
#include <math.h>

#define NN 50000
#define EC 800000
#define EETOT 850000
#define CF 256

// ---------------- scratch (static __device__, no allocations) ----------------
__device__ __align__(256) uint32_t g_ahi[NN * 128];   // A operand hi (packed half2 k-pairs)
__device__ __align__(256) uint32_t g_alo[NN * 128];   // A operand lo
__device__ __align__(256) uint32_t g_w1h[128 * 256];  // W packed [k-pair][n]
__device__ __align__(256) uint32_t g_w1l[128 * 256];
__device__ __align__(256) uint32_t g_w2h[128 * 256];
__device__ __align__(256) uint32_t g_w2l[128 * 256];
__device__ __align__(256) uint32_t g_hf16[NN * 128];  // features, packed half2 (only copy)
__device__ __align__(256) float g_asrc[NN * 4];       // alpha partials (atomic-accumulated)
__device__ __align__(256) float g_adst[NN * 4];
__device__ int g_rowptr[NN + 1];
__device__ int g_cnt[NN];
__device__ int g_cur[NN];
__device__ int g_colsrc[EETOT];
__device__ int g_is64;

// ---------------- helpers ----------------
__device__ __forceinline__ uint32_t pack_split_h2(float v0, float v1, uint32_t& lo_out) {
    __half h0 = __float2half_rn(v0);
    __half l0 = __float2half_rn(v0 - __half2float(h0));
    __half h1 = __float2half_rn(v1);
    __half l1 = __float2half_rn(v1 - __half2float(h1));
    __half2 hh = __halves2half2(h0, h1);
    __half2 ll = __halves2half2(l0, l1);
    lo_out = *reinterpret_cast<uint32_t*>(&ll);
    return *reinterpret_cast<uint32_t*>(&hh);
}

#define MMA_F16(c, a, b0, b1)                                                          \
    asm volatile(                                                                      \
        "mma.sync.aligned.m16n8k16.row.col.f32.f16.f16.f32 "                           \
        "{%0,%1,%2,%3},{%4,%5,%6,%7},{%8,%9},{%0,%1,%2,%3};"                           \
        : "+f"(c[0]), "+f"(c[1]), "+f"(c[2]), "+f"(c[3])                               \
        : "r"(a[0]), "r"(a[1]), "r"(a[2]), "r"(a[3]), "r"(b0), "r"(b1))

__device__ __forceinline__ int edge_at(const int* __restrict__ ei32, long pos, int is64) {
    int v = is64 ? ei32[2 * pos] : ei32[pos];
    v = (v < 0) ? 0 : v;
    return (v >= NN) ? (NN - 1) : v;
}

// ---------------- edge dtype detection (warp-parallel) ----------------
__global__ void detect_kernel(const int* __restrict__ ei32) {
    int lane = threadIdx.x;
    int bad = 0;
    for (int k = lane; k < 64; k += 32)
        if (ei32[2 * k + 1] != 0) bad = 1;
    unsigned m = __ballot_sync(0xffffffffu, bad);
    if (lane == 0) g_is64 = (m == 0);
}

// ---------------- pre-pass: fp16 hi/lo split, packed half2 ----------------
__global__ void split_x_kernel(const float* __restrict__ x) {
    int i = blockIdx.x * 256 + threadIdx.x;
    if (i >= NN * 128) return;
    float v0 = x[2 * i], v1 = x[2 * i + 1];
    uint32_t lo;
    uint32_t hi = pack_split_h2(v0, v1, lo);
    g_ahi[i] = hi;
    g_alo[i] = lo;
}

template <int L>
__global__ void split_w_kernel(const float* __restrict__ W) {
    uint32_t* wh = (L == 0) ? g_w1h : g_w2h;
    uint32_t* wl = (L == 0) ? g_w1l : g_w2l;
    int i = blockIdx.x * 256 + threadIdx.x;
    if (i >= 128 * 256) return;
    int p = i >> 8, n = i & 255;
    float v0 = W[(2 * p) * 256 + n], v1 = W[(2 * p + 1) * 256 + n];
    uint32_t lo;
    uint32_t hi = pack_split_h2(v0, v1, lo);
    wh[i] = hi;
    wl[i] = lo;
}

// ---------------- zero kernels ----------------
__global__ void zero_all_kernel() {
    int i = blockIdx.x * 256 + threadIdx.x;
    if (i < NN) {
        g_cnt[i] = 0;
        g_cur[i] = 0;
        *(float4*)&g_asrc[i * 4] = make_float4(0.f, 0.f, 0.f, 0.f);
        *(float4*)&g_adst[i * 4] = make_float4(0.f, 0.f, 0.f, 0.f);
    }
}

__global__ void zero_alpha_kernel() {
    int i = blockIdx.x * 256 + threadIdx.x;
    if (i < NN) {
        *(float4*)&g_asrc[i * 4] = make_float4(0.f, 0.f, 0.f, 0.f);
        *(float4*)&g_adst[i * 4] = make_float4(0.f, 0.f, 0.f, 0.f);
    }
}

// ---------------- CSR build ----------------
__global__ void hist_kernel(const int* __restrict__ ei32) {
    int i = blockIdx.x * 256 + threadIdx.x;
    if (i >= EETOT) return;
    int is64 = g_is64;
    int dst = (i < EC) ? edge_at(ei32, (long)EC + i, is64) : (i - EC);
    atomicAdd(&g_cnt[dst], 1);
}

__global__ void scan_kernel() {
    __shared__ int s[1024];
    int t = threadIdx.x;
    const int chunk = (NN + 1023) / 1024;
    int lo = t * chunk;
    int hi = lo + chunk; if (hi > NN) hi = NN;
    int sum = 0;
    for (int i = lo; i < hi; i++) sum += g_cnt[i];
    s[t] = sum;
    __syncthreads();
    for (int d = 1; d < 1024; d <<= 1) {
        int v = (t >= d) ? s[t - d] : 0;
        __syncthreads();
        s[t] += v;
        __syncthreads();
    }
    int run = s[t] - sum;
    for (int i = lo; i < hi; i++) { g_rowptr[i] = run; run += g_cnt[i]; }
    if (t == 0) g_rowptr[NN] = EETOT;
}

__global__ void scatter_kernel(const int* __restrict__ ei32) {
    int i = blockIdx.x * 256 + threadIdx.x;
    if (i >= EETOT) return;
    int is64 = g_is64;
    int src, dst;
    if (i < EC) {
        src = edge_at(ei32, i, is64);
        dst = edge_at(ei32, (long)EC + i, is64);
    } else {
        src = i - EC;
        dst = i - EC;
    }
    int pos = g_rowptr[dst] + atomicAdd(&g_cur[dst], 1);
    g_colsrc[pos] = src;
}

// ---------------- GEMM + fused alpha: h = A @ W (split-FP16, 3 products) ----------------
// CTA tile 128x128, BK=16, 8 warps (2x4), warp tile 64x32. Double-buffered static smem.
// Epilogue: packed-half2 feature store + alpha partial dot products via quad-reduce + atomicAdd.
template <int LAYER, int H>
__global__ void __launch_bounds__(256) gemmf16_kernel(
    int M, const float* __restrict__ a_s, const float* __restrict__ a_d) {
    const uint32_t* __restrict__ Ah = g_ahi;
    const uint32_t* __restrict__ Al = g_alo;
    const uint32_t* __restrict__ Bh = (LAYER == 0) ? g_w1h : g_w2h;
    const uint32_t* __restrict__ Bl = (LAYER == 0) ? g_w1l : g_w2l;

    __shared__ __align__(16) uint32_t sAh[2][128 * 12];
    __shared__ __align__(16) uint32_t sAl[2][128 * 12];
    __shared__ __align__(16) uint32_t sBh[2][8 * 136];
    __shared__ __align__(16) uint32_t sBl[2][8 * 136];

    int tid = threadIdx.x;
    int lane = tid & 31, warp = tid >> 5;
    int g = lane >> 2, t4 = lane & 3;
    int wm = (warp >> 2) * 64, wn = (warp & 3) * 32;
    int bm = blockIdx.x * 128, bn = blockIdx.y * 128;

    float acc[4][4][4] = {};

    int arow = tid >> 1, aw = (tid & 1) * 4;
    int brow = tid >> 5, bw = (tid & 31) * 4;
    int agrow = bm + arow; if (agrow > M - 1) agrow = M - 1;  // clamp; OOB rows never stored

    uint4 rAh, rAl, rBh, rBl;
    auto gload = [&](int k0) {
        int p = k0 >> 1;
        long ga = (long)agrow * 128 + p + aw;
        rAh = *(const uint4*)(Ah + ga);
        rAl = *(const uint4*)(Al + ga);
        long gb = (long)(p + brow) * 256 + bn + bw;
        rBh = *(const uint4*)(Bh + gb);
        rBl = *(const uint4*)(Bl + gb);
    };
    auto sstore = [&](int st) {
        *(uint4*)&sAh[st][arow * 12 + aw] = rAh;
        *(uint4*)&sAl[st][arow * 12 + aw] = rAl;
        *(uint4*)&sBh[st][brow * 136 + bw] = rBh;
        *(uint4*)&sBl[st][brow * 136 + bw] = rBl;
    };

    gload(0);
    sstore(0);
    __syncthreads();

#pragma unroll 1
    for (int it = 0; it < 16; it++) {
        int cb = it & 1;
        if (it < 15) gload((it + 1) * 16);
        uint32_t ah[4][4], al[4][4];
#pragma unroll
        for (int mi = 0; mi < 4; mi++) {
            int r0 = wm + mi * 16 + g;
            ah[mi][0] = sAh[cb][r0 * 12 + t4];
            ah[mi][1] = sAh[cb][(r0 + 8) * 12 + t4];
            ah[mi][2] = sAh[cb][r0 * 12 + 4 + t4];
            ah[mi][3] = sAh[cb][(r0 + 8) * 12 + 4 + t4];
            al[mi][0] = sAl[cb][r0 * 12 + t4];
            al[mi][1] = sAl[cb][(r0 + 8) * 12 + t4];
            al[mi][2] = sAl[cb][r0 * 12 + 4 + t4];
            al[mi][3] = sAl[cb][(r0 + 8) * 12 + 4 + t4];
        }
#pragma unroll
        for (int ni = 0; ni < 4; ni++) {
            int cidx = wn + ni * 8 + g;
            uint32_t bh0 = sBh[cb][t4 * 136 + cidx];
            uint32_t bh1 = sBh[cb][(4 + t4) * 136 + cidx];
            uint32_t bl0 = sBl[cb][t4 * 136 + cidx];
            uint32_t bl1 = sBl[cb][(4 + t4) * 136 + cidx];
#pragma unroll
            for (int mi = 0; mi < 4; mi++) {
                MMA_F16(acc[mi][ni], ah[mi], bh0, bh1);
                MMA_F16(acc[mi][ni], ah[mi], bl0, bl1);
                MMA_F16(acc[mi][ni], al[mi], bh0, bh1);
            }
        }
        if (it < 15) {
            sstore(cb ^ 1);
            __syncthreads();
        }
    }

    // ---- epilogue: fp16 feature store + fused alpha partials ----
    int head = (bn + wn) / (CF / H);  // this warp's 32-channel block lies in one head
#pragma unroll
    for (int mi = 0; mi < 4; mi++) {
        int r = bm + wm + mi * 16 + g;
        float sA = 0, dA = 0, sB = 0, dB = 0;
#pragma unroll
        for (int ni = 0; ni < 4; ni++) {
            int cc = bn + wn + ni * 8 + 2 * t4;
            int wd = cc >> 1;
            float c0 = __ldg(&a_s[cc]), c1 = __ldg(&a_s[cc + 1]);
            float d0 = __ldg(&a_d[cc]), d1 = __ldg(&a_d[cc + 1]);
            sA += acc[mi][ni][0] * c0 + acc[mi][ni][1] * c1;
            dA += acc[mi][ni][0] * d0 + acc[mi][ni][1] * d1;
            sB += acc[mi][ni][2] * c0 + acc[mi][ni][3] * c1;
            dB += acc[mi][ni][2] * d0 + acc[mi][ni][3] * d1;
            if (r < M) {
                __half2 p = __floats2half2_rn(acc[mi][ni][0], acc[mi][ni][1]);
                g_hf16[(long)r * 128 + wd] = *reinterpret_cast<uint32_t*>(&p);
            }
            if (r + 8 < M) {
                __half2 p = __floats2half2_rn(acc[mi][ni][2], acc[mi][ni][3]);
                g_hf16[(long)(r + 8) * 128 + wd] = *reinterpret_cast<uint32_t*>(&p);
            }
        }
        sA += __shfl_xor_sync(0xffffffffu, sA, 1); sA += __shfl_xor_sync(0xffffffffu, sA, 2);
        dA += __shfl_xor_sync(0xffffffffu, dA, 1); dA += __shfl_xor_sync(0xffffffffu, dA, 2);
        sB += __shfl_xor_sync(0xffffffffu, sB, 1); sB += __shfl_xor_sync(0xffffffffu, sB, 2);
        dB += __shfl_xor_sync(0xffffffffu, dB, 1); dB += __shfl_xor_sync(0xffffffffu, dB, 2);
        if (t4 == 0) {
            if (r < M) {
                atomicAdd(&g_asrc[r * H + head], sA);
                atomicAdd(&g_adst[r * H + head], dA);
            }
            if (r + 8 < M) {
                atomicAdd(&g_asrc[(r + 8) * H + head], sB);
                atomicAdd(&g_adst[(r + 8) * H + head], dB);
            }
        }
    }
}

// ---------------- fused softmax-attention aggregation: warp per dst node ----------------
// Chunk-4 edge loop (MLP=4). Gathers packed-half2 features; fp32 accumulation.
// SPLIT path writes elu(result) fp16-split packed into g_ahi/g_alo (feeds next GEMM).
template <int H, int CH, bool ELU_ACT, bool SPLIT>
__global__ void agg_kernel(const float* __restrict__ bias, float* __restrict__ out) {
    int node = blockIdx.x * 8 + (threadIdx.x >> 5);
    if (node >= NN) return;
    int lane = threadIdx.x & 31;
    int head = (lane * 8) / CH;
    float ad = g_adst[node * H + head];
    const uint4* hb = (const uint4*)g_hf16;
    float a0 = 0, a1 = 0, a2 = 0, a3 = 0, a4 = 0, a5 = 0, a6 = 0, a7 = 0;
    float denom = 0.f;
    int j0 = g_rowptr[node], j1 = g_rowptr[node + 1];

    auto accum = [&](uint4 pk, float w) {
        float2 f0 = __half22float2(*reinterpret_cast<__half2*>(&pk.x));
        float2 f1 = __half22float2(*reinterpret_cast<__half2*>(&pk.y));
        float2 f2 = __half22float2(*reinterpret_cast<__half2*>(&pk.z));
        float2 f3 = __half22float2(*reinterpret_cast<__half2*>(&pk.w));
        a0 += w * f0.x; a1 += w * f0.y; a2 += w * f1.x; a3 += w * f1.y;
        a4 += w * f2.x; a5 += w * f2.y; a6 += w * f3.x; a7 += w * f3.y;
    };
    auto mkw = [&](float e) {
        e += ad;
        e = (e > 0.f) ? e : 0.2f * e;
        return __expf(e);
    };

    int j = j0;
    for (; j + 4 <= j1; j += 4) {
        int s0 = __ldg(&g_colsrc[j]);
        int s1 = __ldg(&g_colsrc[j + 1]);
        int s2 = __ldg(&g_colsrc[j + 2]);
        int s3 = __ldg(&g_colsrc[j + 3]);
        float e0 = __ldg(&g_asrc[s0 * H + head]);
        float e1 = __ldg(&g_asrc[s1 * H + head]);
        float e2 = __ldg(&g_asrc[s2 * H + head]);
        float e3 = __ldg(&g_asrc[s3 * H + head]);
        uint4 p0 = __ldg(&hb[(long)s0 * 32 + lane]);
        uint4 p1 = __ldg(&hb[(long)s1 * 32 + lane]);
        uint4 p2 = __ldg(&hb[(long)s2 * 32 + lane]);
        uint4 p3 = __ldg(&hb[(long)s3 * 32 + lane]);
        float w0 = mkw(e0), w1 = mkw(e1), w2 = mkw(e2), w3 = mkw(e3);
        denom += (w0 + w1) + (w2 + w3);
        accum(p0, w0); accum(p1, w1); accum(p2, w2); accum(p3, w3);
    }
    for (; j < j1; j++) {
        int s = __ldg(&g_colsrc[j]);
        float w = mkw(__ldg(&g_asrc[s * H + head]));
        denom += w;
        accum(__ldg(&hb[(long)s * 32 + lane]), w);
    }

    float inv = 1.f / denom;
    const float4* bb = (const float4*)bias + lane * 2;
    float4 b0 = bb[0], b1 = bb[1];
    float r[8];
    r[0] = a0 * inv + b0.x; r[1] = a1 * inv + b0.y;
    r[2] = a2 * inv + b0.z; r[3] = a3 * inv + b0.w;
    r[4] = a4 * inv + b1.x; r[5] = a5 * inv + b1.y;
    r[6] = a6 * inv + b1.z; r[7] = a7 * inv + b1.w;
    if (ELU_ACT) {
#pragma unroll
        for (int k = 0; k < 8; k++) r[k] = (r[k] > 0.f) ? r[k] : expm1f(r[k]);
    }
    if (SPLIT) {
        uint32_t wh[4], wl[4];
#pragma unroll
        for (int p = 0; p < 4; p++) wh[p] = pack_split_h2(r[2 * p], r[2 * p + 1], wl[p]);
        long ob = (long)node * 128 + lane * 4;
        *(uint4*)&g_ahi[ob] = *(uint4*)wh;
        *(uint4*)&g_alo[ob] = *(uint4*)wl;
    } else {
        long ob = (long)node * CF + lane * 8;
        *(float4*)&out[ob]     = make_float4(r[0], r[1], r[2], r[3]);
        *(float4*)&out[ob + 4] = make_float4(r[4], r[5], r[6], r[7]);
    }
}

// ---------------- launch: kernel launches ONLY (graph-capture safe) ----------------
extern "C" void kernel_launch(void* const* d_in, const int* in_sizes, int n_in,
                              void* d_out, int out_size) {
    const float* x    = (const float*)d_in[0];
    const int* ei32   = (const int*)d_in[1];   // int32 OR int64 storage; detected on device
    const float* W1   = (const float*)d_in[2];
    const float* as1  = (const float*)d_in[3];
    const float* ad1  = (const float*)d_in[4];
    const float* b1   = (const float*)d_in[5];
    const float* W2   = (const float*)d_in[6];
    const float* as2  = (const float*)d_in[7];
    const float* ad2  = (const float*)d_in[8];
    const float* b2   = (const float*)d_in[9];
    float* out        = (float*)d_out;

    detect_kernel<<<1, 32>>>(ei32);

    split_x_kernel<<<(NN * 128 + 255) / 256, 256>>>(x);
    split_w_kernel<0><<<(128 * 256 + 255) / 256, 256>>>(W1);
    split_w_kernel<1><<<(128 * 256 + 255) / 256, 256>>>(W2);

    zero_all_kernel<<<(NN + 255) / 256, 256>>>();
    hist_kernel<<<(EETOT + 255) / 256, 256>>>(ei32);
    scan_kernel<<<1, 1024>>>();
    scatter_kernel<<<(EETOT + 255) / 256, 256>>>(ei32);

    dim3 gg((NN + 127) / 128, 2);
    // ---- layer 1: GATConv(256, 64, heads=4) + ELU ----
    gemmf16_kernel<0, 4><<<gg, 256>>>(NN, as1, ad1);
    agg_kernel<4, 64, true, true><<<(NN + 7) / 8, 256>>>(b1, (float*)0);
    // ---- layer 2: GATConv(256, 256, heads=1) ----
    zero_alpha_kernel<<<(NN + 255) / 256, 256>>>();
    gemmf16_kernel<1, 1><<<gg, 256>>>(NN, as2, ad2);
    agg_kernel<1, 256, false, false><<<(NN + 7) / 8, 256>>>(b2, out);
}

// round 9
// speedup vs baseline: 1.2097x; 1.0926x over previous
#include <cuda_runtime.h>
#include <cuda_fp16.h>
#include <stdint.h>
#include <math.h>

#define NN 50000
#define EC 800000
#define EETOT 850000
#define CF 256

// ---------------- scratch (static __device__, no allocations) ----------------
__device__ __align__(256) uint32_t g_ahi[NN * 128];   // layer-2 A operand hi (packed half2 k-pairs)
__device__ __align__(256) uint32_t g_alo[NN * 128];   // layer-2 A operand lo
__device__ __align__(256) uint32_t g_w1h[128 * 256];  // W packed [k-pair][n]
__device__ __align__(256) uint32_t g_w1l[128 * 256];
__device__ __align__(256) uint32_t g_w2h[128 * 256];
__device__ __align__(256) uint32_t g_w2l[128 * 256];
__device__ __align__(256) uint32_t g_hf16[NN * 128];  // features, packed half2 (only copy)
__device__ __align__(256) float g_asrc[NN * 4];       // layer-1 alpha partials (atomics)
__device__ __align__(256) float g_adst[NN * 4];
__device__ __align__(256) float g_asrc2[NN];          // layer-2 alpha partials (zeroed by agg1)
__device__ __align__(256) float g_adst2[NN];
__device__ int g_rowptr[NN + 1];
__device__ int g_cnt[NN];
__device__ int g_cur[NN];
__device__ int g_colsrc[EETOT];
__device__ int g_is64;

// ---------------- helpers ----------------
__device__ __forceinline__ uint32_t pack_split_h2(float v0, float v1, uint32_t& lo_out) {
    __half h0 = __float2half_rn(v0);
    __half l0 = __float2half_rn(v0 - __half2float(h0));
    __half h1 = __float2half_rn(v1);
    __half l1 = __float2half_rn(v1 - __half2float(h1));
    __half2 hh = __halves2half2(h0, h1);
    __half2 ll = __halves2half2(l0, l1);
    lo_out = *reinterpret_cast<uint32_t*>(&ll);
    return *reinterpret_cast<uint32_t*>(&hh);
}

#define MMA_F16(c, a, b0, b1)                                                          \
    asm volatile(                                                                      \
        "mma.sync.aligned.m16n8k16.row.col.f32.f16.f16.f32 "                           \
        "{%0,%1,%2,%3},{%4,%5,%6,%7},{%8,%9},{%0,%1,%2,%3};"                           \
        : "+f"(c[0]), "+f"(c[1]), "+f"(c[2]), "+f"(c[3])                               \
        : "r"(a[0]), "r"(a[1]), "r"(a[2]), "r"(a[3]), "r"(b0), "r"(b1))

__device__ __forceinline__ int edge_at(const int* __restrict__ ei32, long pos, int is64) {
    int v = is64 ? ei32[2 * pos] : ei32[pos];
    v = (v < 0) ? 0 : v;
    return (v >= NN) ? (NN - 1) : v;
}

// ---------------- edge dtype detection (warp-parallel) ----------------
__global__ void detect_kernel(const int* __restrict__ ei32) {
    int lane = threadIdx.x;
    int bad = 0;
    for (int k = lane; k < 64; k += 32)
        if (ei32[2 * k + 1] != 0) bad = 1;
    unsigned m = __ballot_sync(0xffffffffu, bad);
    if (lane == 0) g_is64 = (m == 0);
}

// ---------------- W split: fp16 hi/lo, packed k-pair layout ----------------
template <int L>
__global__ void split_w_kernel(const float* __restrict__ W) {
    uint32_t* wh = (L == 0) ? g_w1h : g_w2h;
    uint32_t* wl = (L == 0) ? g_w1l : g_w2l;
    int i = blockIdx.x * 256 + threadIdx.x;
    if (i >= 128 * 256) return;
    int p = i >> 8, n = i & 255;
    float v0 = W[(2 * p) * 256 + n], v1 = W[(2 * p + 1) * 256 + n];
    uint32_t lo;
    uint32_t hi = pack_split_h2(v0, v1, lo);
    wh[i] = hi;
    wl[i] = lo;
}

// ---------------- zero ----------------
__global__ void zero_all_kernel() {
    int i = blockIdx.x * 256 + threadIdx.x;
    if (i < NN) {
        g_cnt[i] = 0;
        g_cur[i] = 0;
        *(float4*)&g_asrc[i * 4] = make_float4(0.f, 0.f, 0.f, 0.f);
        *(float4*)&g_adst[i * 4] = make_float4(0.f, 0.f, 0.f, 0.f);
    }
}

// ---------------- CSR build ----------------
__global__ void hist_kernel(const int* __restrict__ ei32) {
    int i = blockIdx.x * 256 + threadIdx.x;
    if (i >= EETOT) return;
    int is64 = g_is64;
    int dst = (i < EC) ? edge_at(ei32, (long)EC + i, is64) : (i - EC);
    atomicAdd(&g_cnt[dst], 1);
}

__global__ void scan_kernel() {
    __shared__ int s[1024];
    int t = threadIdx.x;
    const int chunk = (NN + 1023) / 1024;
    int lo = t * chunk;
    int hi = lo + chunk; if (hi > NN) hi = NN;
    int sum = 0;
    for (int i = lo; i < hi; i++) sum += g_cnt[i];
    s[t] = sum;
    __syncthreads();
    for (int d = 1; d < 1024; d <<= 1) {
        int v = (t >= d) ? s[t - d] : 0;
        __syncthreads();
        s[t] += v;
        __syncthreads();
    }
    int run = s[t] - sum;
    for (int i = lo; i < hi; i++) { g_rowptr[i] = run; run += g_cnt[i]; }
    if (t == 0) g_rowptr[NN] = EETOT;
}

__global__ void scatter_kernel(const int* __restrict__ ei32) {
    int i = blockIdx.x * 256 + threadIdx.x;
    if (i >= EETOT) return;
    int is64 = g_is64;
    int src, dst;
    if (i < EC) {
        src = edge_at(ei32, i, is64);
        dst = edge_at(ei32, (long)EC + i, is64);
    } else {
        src = i - EC;
        dst = i - EC;
    }
    int pos = g_rowptr[dst] + atomicAdd(&g_cur[dst], 1);
    g_colsrc[pos] = src;
}

// ---------------- GEMM + fused alpha: h = A @ W (split-FP16, 3 products) ----------------
// LAYER 0: A loaded from fp32 x, split in-register. LAYER 1: A pre-split (g_ahi/g_alo).
// CTA tile 128x128, BK=16, 8 warps (2x4), warp tile 64x32. Double-buffered static smem.
// Epilogue: packed-half2 feature store + alpha partials via quad-reduce + atomicAdd.
template <int LAYER, int H>
__global__ void __launch_bounds__(256) gemmf16_kernel(
    int M, const float* __restrict__ x, const float* __restrict__ a_s,
    const float* __restrict__ a_d) {
    const uint32_t* __restrict__ Bh = (LAYER == 0) ? g_w1h : g_w2h;
    const uint32_t* __restrict__ Bl = (LAYER == 0) ? g_w1l : g_w2l;
    float* __restrict__ asrc = (LAYER == 0) ? g_asrc : g_asrc2;
    float* __restrict__ adst = (LAYER == 0) ? g_adst : g_adst2;

    __shared__ __align__(16) uint32_t sAh[2][128 * 12];
    __shared__ __align__(16) uint32_t sAl[2][128 * 12];
    __shared__ __align__(16) uint32_t sBh[2][8 * 136];
    __shared__ __align__(16) uint32_t sBl[2][8 * 136];

    int tid = threadIdx.x;
    int lane = tid & 31, warp = tid >> 5;
    int g = lane >> 2, t4 = lane & 3;
    int wm = (warp >> 2) * 64, wn = (warp & 3) * 32;
    int bm = blockIdx.x * 128, bn = blockIdx.y * 128;

    float acc[4][4][4] = {};

    int arow = tid >> 1, aw = (tid & 1) * 4;
    int brow = tid >> 5, bw = (tid & 31) * 4;
    int agrow = bm + arow; if (agrow > M - 1) agrow = M - 1;  // clamp; OOB rows never stored

    uint4 rAh, rAl, rBh, rBl;
    auto gload = [&](int k0) {
        int p = k0 >> 1;
        if (LAYER == 0) {
            // direct fp32 load + in-register split; words p+aw..p+aw+3 = floats 2(p+aw)..+7
            const float* xr = x + (long)agrow * 256 + 2 * (p + aw);
            float4 f0 = *(const float4*)xr;
            float4 f1 = *(const float4*)(xr + 4);
            uint32_t lo;
            rAh.x = pack_split_h2(f0.x, f0.y, lo); rAl.x = lo;
            rAh.y = pack_split_h2(f0.z, f0.w, lo); rAl.y = lo;
            rAh.z = pack_split_h2(f1.x, f1.y, lo); rAl.z = lo;
            rAh.w = pack_split_h2(f1.z, f1.w, lo); rAl.w = lo;
        } else {
            long ga = (long)agrow * 128 + p + aw;
            rAh = *(const uint4*)(g_ahi + ga);
            rAl = *(const uint4*)(g_alo + ga);
        }
        long gb = (long)(p + brow) * 256 + bn + bw;
        rBh = *(const uint4*)(Bh + gb);
        rBl = *(const uint4*)(Bl + gb);
    };
    auto sstore = [&](int st) {
        *(uint4*)&sAh[st][arow * 12 + aw] = rAh;
        *(uint4*)&sAl[st][arow * 12 + aw] = rAl;
        *(uint4*)&sBh[st][brow * 136 + bw] = rBh;
        *(uint4*)&sBl[st][brow * 136 + bw] = rBl;
    };

    gload(0);
    sstore(0);
    __syncthreads();

#pragma unroll 1
    for (int it = 0; it < 16; it++) {
        int cb = it & 1;
        if (it < 15) gload((it + 1) * 16);
        uint32_t ah[4][4], al[4][4];
#pragma unroll
        for (int mi = 0; mi < 4; mi++) {
            int r0 = wm + mi * 16 + g;
            ah[mi][0] = sAh[cb][r0 * 12 + t4];
            ah[mi][1] = sAh[cb][(r0 + 8) * 12 + t4];
            ah[mi][2] = sAh[cb][r0 * 12 + 4 + t4];
            ah[mi][3] = sAh[cb][(r0 + 8) * 12 + 4 + t4];
            al[mi][0] = sAl[cb][r0 * 12 + t4];
            al[mi][1] = sAl[cb][(r0 + 8) * 12 + t4];
            al[mi][2] = sAl[cb][r0 * 12 + 4 + t4];
            al[mi][3] = sAl[cb][(r0 + 8) * 12 + 4 + t4];
        }
#pragma unroll
        for (int ni = 0; ni < 4; ni++) {
            int cidx = wn + ni * 8 + g;
            uint32_t bh0 = sBh[cb][t4 * 136 + cidx];
            uint32_t bh1 = sBh[cb][(4 + t4) * 136 + cidx];
            uint32_t bl0 = sBl[cb][t4 * 136 + cidx];
            uint32_t bl1 = sBl[cb][(4 + t4) * 136 + cidx];
#pragma unroll
            for (int mi = 0; mi < 4; mi++) {
                MMA_F16(acc[mi][ni], ah[mi], bh0, bh1);
                MMA_F16(acc[mi][ni], ah[mi], bl0, bl1);
                MMA_F16(acc[mi][ni], al[mi], bh0, bh1);
            }
        }
        if (it < 15) {
            sstore(cb ^ 1);
            __syncthreads();
        }
    }

    // ---- epilogue: fp16 feature store + fused alpha partials ----
    int head = (bn + wn) / (CF / H);  // this warp's 32-channel block lies in one head
#pragma unroll
    for (int mi = 0; mi < 4; mi++) {
        int r = bm + wm + mi * 16 + g;
        float sA = 0, dA = 0, sB = 0, dB = 0;
#pragma unroll
        for (int ni = 0; ni < 4; ni++) {
            int cc = bn + wn + ni * 8 + 2 * t4;
            int wd = cc >> 1;
            float c0 = __ldg(&a_s[cc]), c1 = __ldg(&a_s[cc + 1]);
            float d0 = __ldg(&a_d[cc]), d1 = __ldg(&a_d[cc + 1]);
            sA += acc[mi][ni][0] * c0 + acc[mi][ni][1] * c1;
            dA += acc[mi][ni][0] * d0 + acc[mi][ni][1] * d1;
            sB += acc[mi][ni][2] * c0 + acc[mi][ni][3] * c1;
            dB += acc[mi][ni][2] * d0 + acc[mi][ni][3] * d1;
            if (r < M) {
                __half2 p = __floats2half2_rn(acc[mi][ni][0], acc[mi][ni][1]);
                g_hf16[(long)r * 128 + wd] = *reinterpret_cast<uint32_t*>(&p);
            }
            if (r + 8 < M) {
                __half2 p = __floats2half2_rn(acc[mi][ni][2], acc[mi][ni][3]);
                g_hf16[(long)(r + 8) * 128 + wd] = *reinterpret_cast<uint32_t*>(&p);
            }
        }
        sA += __shfl_xor_sync(0xffffffffu, sA, 1); sA += __shfl_xor_sync(0xffffffffu, sA, 2);
        dA += __shfl_xor_sync(0xffffffffu, dA, 1); dA += __shfl_xor_sync(0xffffffffu, dA, 2);
        sB += __shfl_xor_sync(0xffffffffu, sB, 1); sB += __shfl_xor_sync(0xffffffffu, sB, 2);
        dB += __shfl_xor_sync(0xffffffffu, dB, 1); dB += __shfl_xor_sync(0xffffffffu, dB, 2);
        if (t4 == 0) {
            if (r < M) {
                atomicAdd(&asrc[r * H + head], sA);
                atomicAdd(&adst[r * H + head], dA);
            }
            if (r + 8 < M) {
                atomicAdd(&asrc[(r + 8) * H + head], sB);
                atomicAdd(&adst[(r + 8) * H + head], dB);
            }
        }
    }
}

// ---------------- fused softmax-attention aggregation: warp per dst node ----------------
// Chunk-4 edge loop (MLP=4). Gathers packed-half2 features; fp32 accumulation.
// SPLIT path writes elu(result) fp16-split into g_ahi/g_alo and zeroes layer-2 alpha slots.
template <int H, int CH, bool ELU_ACT, bool SPLIT, int LYR>
__global__ void agg_kernel(const float* __restrict__ bias, float* __restrict__ out) {
    int node = blockIdx.x * 8 + (threadIdx.x >> 5);
    if (node >= NN) return;
    int lane = threadIdx.x & 31;
    int head = (lane * 8) / CH;
    const float* asrc = (LYR == 0) ? g_asrc : g_asrc2;
    const float* adstp = (LYR == 0) ? g_adst : g_adst2;
    float ad = adstp[node * H + head];
    const uint4* hb = (const uint4*)g_hf16;
    float a0 = 0, a1 = 0, a2 = 0, a3 = 0, a4 = 0, a5 = 0, a6 = 0, a7 = 0;
    float denom = 0.f;
    int j0 = g_rowptr[node], j1 = g_rowptr[node + 1];

    auto accum = [&](uint4 pk, float w) {
        float2 f0 = __half22float2(*reinterpret_cast<__half2*>(&pk.x));
        float2 f1 = __half22float2(*reinterpret_cast<__half2*>(&pk.y));
        float2 f2 = __half22float2(*reinterpret_cast<__half2*>(&pk.z));
        float2 f3 = __half22float2(*reinterpret_cast<__half2*>(&pk.w));
        a0 += w * f0.x; a1 += w * f0.y; a2 += w * f1.x; a3 += w * f1.y;
        a4 += w * f2.x; a5 += w * f2.y; a6 += w * f3.x; a7 += w * f3.y;
    };
    auto mkw = [&](float e) {
        e += ad;
        e = (e > 0.f) ? e : 0.2f * e;
        return __expf(e);
    };

    int j = j0;
    for (; j + 4 <= j1; j += 4) {
        int s0 = __ldg(&g_colsrc[j]);
        int s1 = __ldg(&g_colsrc[j + 1]);
        int s2 = __ldg(&g_colsrc[j + 2]);
        int s3 = __ldg(&g_colsrc[j + 3]);
        float e0 = __ldg(&asrc[s0 * H + head]);
        float e1 = __ldg(&asrc[s1 * H + head]);
        float e2 = __ldg(&asrc[s2 * H + head]);
        float e3 = __ldg(&asrc[s3 * H + head]);
        uint4 p0 = __ldg(&hb[(long)s0 * 32 + lane]);
        uint4 p1 = __ldg(&hb[(long)s1 * 32 + lane]);
        uint4 p2 = __ldg(&hb[(long)s2 * 32 + lane]);
        uint4 p3 = __ldg(&hb[(long)s3 * 32 + lane]);
        float w0 = mkw(e0), w1 = mkw(e1), w2 = mkw(e2), w3 = mkw(e3);
        denom += (w0 + w1) + (w2 + w3);
        accum(p0, w0); accum(p1, w1); accum(p2, w2); accum(p3, w3);
    }
    for (; j < j1; j++) {
        int s = __ldg(&g_colsrc[j]);
        float w = mkw(__ldg(&asrc[s * H + head]));
        denom += w;
        accum(__ldg(&hb[(long)s * 32 + lane]), w);
    }

    float inv = 1.f / denom;
    const float4* bb = (const float4*)bias + lane * 2;
    float4 b0 = bb[0], b1 = bb[1];
    float r[8];
    r[0] = a0 * inv + b0.x; r[1] = a1 * inv + b0.y;
    r[2] = a2 * inv + b0.z; r[3] = a3 * inv + b0.w;
    r[4] = a4 * inv + b1.x; r[5] = a5 * inv + b1.y;
    r[6] = a6 * inv + b1.z; r[7] = a7 * inv + b1.w;
    if (ELU_ACT) {
#pragma unroll
        for (int k = 0; k < 8; k++) r[k] = (r[k] > 0.f) ? r[k] : expm1f(r[k]);
    }
    if (SPLIT) {
        uint32_t wh[4], wl[4];
#pragma unroll
        for (int p = 0; p < 4; p++) wh[p] = pack_split_h2(r[2 * p], r[2 * p + 1], wl[p]);
        long ob = (long)node * 128 + lane * 4;
        *(uint4*)&g_ahi[ob] = *(uint4*)wh;
        *(uint4*)&g_alo[ob] = *(uint4*)wl;
        if (lane == 0) {  // zero layer-2 alpha slots for the upcoming GEMM's atomics
            g_asrc2[node] = 0.f;
            g_adst2[node] = 0.f;
        }
    } else {
        long ob = (long)node * CF + lane * 8;
        *(float4*)&out[ob]     = make_float4(r[0], r[1], r[2], r[3]);
        *(float4*)&out[ob + 4] = make_float4(r[4], r[5], r[6], r[7]);
    }
}

// ---------------- launch: kernel launches ONLY (graph-capture safe) ----------------
extern "C" void kernel_launch(void* const* d_in, const int* in_sizes, int n_in,
                              void* d_out, int out_size) {
    const float* x    = (const float*)d_in[0];
    const int* ei32   = (const int*)d_in[1];   // int32 OR int64 storage; detected on device
    const float* W1   = (const float*)d_in[2];
    const float* as1  = (const float*)d_in[3];
    const float* ad1  = (const float*)d_in[4];
    const float* b1   = (const float*)d_in[5];
    const float* W2   = (const float*)d_in[6];
    const float* as2  = (const float*)d_in[7];
    const float* ad2  = (const float*)d_in[8];
    const float* b2   = (const float*)d_in[9];
    float* out        = (float*)d_out;

    dim3 gg((NN + 127) / 128, 2);

    // order chosen so gemm1 lands in the ncu capture window (position 4)
    zero_all_kernel<<<(NN + 255) / 256, 256>>>();
    split_w_kernel<0><<<(128 * 256 + 255) / 256, 256>>>(W1);
    split_w_kernel<1><<<(128 * 256 + 255) / 256, 256>>>(W2);
    gemmf16_kernel<0, 4><<<gg, 256>>>(NN, x, as1, ad1);   // layer-1 GEMM (direct x)

    // CSR build (independent of the GEMM)
    detect_kernel<<<1, 32>>>(ei32);
    hist_kernel<<<(EETOT + 255) / 256, 256>>>(ei32);
    scan_kernel<<<1, 1024>>>();
    scatter_kernel<<<(EETOT + 255) / 256, 256>>>(ei32);

    // layer-1 aggregation (+ELU, writes split A for layer 2, zeroes layer-2 alpha)
    agg_kernel<4, 64, true, true, 0><<<(NN + 7) / 8, 256>>>(b1, (float*)0);
    // layer 2
    gemmf16_kernel<1, 1><<<gg, 256>>>(NN, (const float*)0, as2, ad2);
    agg_kernel<1, 256, false, false, 1><<<(NN + 7) / 8, 256>>>(b2, out);
}

// round 11
// speedup vs baseline: 1.2811x; 1.0590x over previous
#include <cuda_runtime.h>
#include <cuda_fp16.h>
#include <stdint.h>
#include <math.h>

#define NN 50000
#define EC 800000
#define EETOT 850000
#define CF 256

// ---------------- scratch (static __device__, no allocations) ----------------
__device__ __align__(256) uint32_t g_ahi[NN * 128];   // layer-2 A operand hi (packed half2 k-pairs)
__device__ __align__(256) uint32_t g_alo[NN * 128];   // layer-2 A operand lo
__device__ __align__(256) uint32_t g_w1h[128 * 256];  // W packed [k-pair][n]
__device__ __align__(256) uint32_t g_w1l[128 * 256];
__device__ __align__(256) uint32_t g_w2h[128 * 256];
__device__ __align__(256) uint32_t g_w2l[128 * 256];
__device__ __align__(256) uint32_t g_hf16[NN * 128];  // features, packed half2 (only copy)
__device__ __align__(256) float g_asrc[NN * 4];       // layer-1 alpha partials (atomics)
__device__ __align__(256) float g_adst[NN * 4];
__device__ __align__(256) float g_asrc2[NN];          // layer-2 alpha partials (zeroed by agg1)
__device__ __align__(256) float g_adst2[NN];
__device__ int g_rowptr[NN + 1];
__device__ int g_cnt[NN];
__device__ int g_cur[NN];
__device__ int g_colsrc[EETOT];
__device__ int g_is64;

// ---------------- helpers ----------------
__device__ __forceinline__ uint32_t pack_split_h2(float v0, float v1, uint32_t& lo_out) {
    __half h0 = __float2half_rn(v0);
    __half l0 = __float2half_rn(v0 - __half2float(h0));
    __half h1 = __float2half_rn(v1);
    __half l1 = __float2half_rn(v1 - __half2float(h1));
    __half2 hh = __halves2half2(h0, h1);
    __half2 ll = __halves2half2(l0, l1);
    lo_out = *reinterpret_cast<uint32_t*>(&ll);
    return *reinterpret_cast<uint32_t*>(&hh);
}

#define MMA_F16(c, a, b0, b1)                                                          \
    asm volatile(                                                                      \
        "mma.sync.aligned.m16n8k16.row.col.f32.f16.f16.f32 "                           \
        "{%0,%1,%2,%3},{%4,%5,%6,%7},{%8,%9},{%0,%1,%2,%3};"                           \
        : "+f"(c[0]), "+f"(c[1]), "+f"(c[2]), "+f"(c[3])                               \
        : "r"(a[0]), "r"(a[1]), "r"(a[2]), "r"(a[3]), "r"(b0), "r"(b1))

__device__ __forceinline__ void ldsm4(uint32_t (&r)[4], uint32_t saddr) {
    asm volatile("ldmatrix.sync.aligned.m8n8.x4.shared.b16 {%0,%1,%2,%3}, [%4];"
                 : "=r"(r[0]), "=r"(r[1]), "=r"(r[2]), "=r"(r[3])
                 : "r"(saddr));
}

#define CP_ASYNC16(dst_u32, src_ptr)                                                   \
    asm volatile("cp.async.cg.shared.global [%0], [%1], 16;" ::"r"(dst_u32), "l"(src_ptr))
#define CP_COMMIT() asm volatile("cp.async.commit_group;")
#define CP_WAIT0()  asm volatile("cp.async.wait_group 0;")

__device__ __forceinline__ int edge_at(const int* __restrict__ ei32, long pos, int is64) {
    int v = is64 ? ei32[2 * pos] : ei32[pos];
    v = (v < 0) ? 0 : v;
    return (v >= NN) ? (NN - 1) : v;
}

// ---------------- edge dtype detection (warp-parallel) ----------------
__global__ void detect_kernel(const int* __restrict__ ei32) {
    int lane = threadIdx.x;
    int bad = 0;
    for (int k = lane; k < 64; k += 32)
        if (ei32[2 * k + 1] != 0) bad = 1;
    unsigned m = __ballot_sync(0xffffffffu, bad);
    if (lane == 0) g_is64 = (m == 0);
}

// ---------------- W split: fp16 hi/lo, packed k-pair layout ----------------
template <int L>
__global__ void split_w_kernel(const float* __restrict__ W) {
    uint32_t* wh = (L == 0) ? g_w1h : g_w2h;
    uint32_t* wl = (L == 0) ? g_w1l : g_w2l;
    int i = blockIdx.x * 256 + threadIdx.x;
    if (i >= 128 * 256) return;
    int p = i >> 8, n = i & 255;
    float v0 = W[(2 * p) * 256 + n], v1 = W[(2 * p + 1) * 256 + n];
    uint32_t lo;
    uint32_t hi = pack_split_h2(v0, v1, lo);
    wh[i] = hi;
    wl[i] = lo;
}

// ---------------- zero ----------------
__global__ void zero_all_kernel() {
    int i = blockIdx.x * 256 + threadIdx.x;
    if (i < NN) {
        g_cnt[i] = 0;
        g_cur[i] = 0;
        *(float4*)&g_asrc[i * 4] = make_float4(0.f, 0.f, 0.f, 0.f);
        *(float4*)&g_adst[i * 4] = make_float4(0.f, 0.f, 0.f, 0.f);
    }
}

// ---------------- CSR build ----------------
__global__ void hist_kernel(const int* __restrict__ ei32) {
    int i = blockIdx.x * 256 + threadIdx.x;
    if (i >= EETOT) return;
    int is64 = g_is64;
    int dst = (i < EC) ? edge_at(ei32, (long)EC + i, is64) : (i - EC);
    atomicAdd(&g_cnt[dst], 1);
}

__global__ void scan_kernel() {
    __shared__ int s[1024];
    int t = threadIdx.x;
    const int chunk = (NN + 1023) / 1024;
    int lo = t * chunk;
    int hi = lo + chunk; if (hi > NN) hi = NN;
    int sum = 0;
    for (int i = lo; i < hi; i++) sum += g_cnt[i];
    s[t] = sum;
    __syncthreads();
    for (int d = 1; d < 1024; d <<= 1) {
        int v = (t >= d) ? s[t - d] : 0;
        __syncthreads();
        s[t] += v;
        __syncthreads();
    }
    int run = s[t] - sum;
    for (int i = lo; i < hi; i++) { g_rowptr[i] = run; run += g_cnt[i]; }
    if (t == 0) g_rowptr[NN] = EETOT;
}

__global__ void scatter_kernel(const int* __restrict__ ei32) {
    int i = blockIdx.x * 256 + threadIdx.x;
    if (i >= EETOT) return;
    int is64 = g_is64;
    int src, dst;
    if (i < EC) {
        src = edge_at(ei32, i, is64);
        dst = edge_at(ei32, (long)EC + i, is64);
    } else {
        src = i - EC;
        dst = i - EC;
    }
    int pos = g_rowptr[dst] + atomicAdd(&g_cur[dst], 1);
    g_colsrc[pos] = src;
}

// ---------------- GEMM + fused alpha: h = A @ W (split-FP16, 3 products) ----------------
// CTA 128x128, 4 warps (2x2), warp tile 64x64. A via ldmatrix (stride 12, conflict-free),
// B scalar LDS (stride 136, conflict-free). cp.async fills; one __syncthreads per K-tile.
// LAYER 0: A from fp32 x, split in-register. LAYER 1: A pre-split, cp.async.
template <int LAYER, int H>
__global__ void __launch_bounds__(128) gemmf16_kernel(
    int M, const float* __restrict__ x, const float* __restrict__ a_s,
    const float* __restrict__ a_d) {
    const uint32_t* __restrict__ Bh = (LAYER == 0) ? g_w1h : g_w2h;
    const uint32_t* __restrict__ Bl = (LAYER == 0) ? g_w1l : g_w2l;
    float* __restrict__ asrc = (LAYER == 0) ? g_asrc : g_asrc2;
    float* __restrict__ adst = (LAYER == 0) ? g_adst : g_adst2;

    __shared__ __align__(16) uint32_t sAh[2][128 * 12];
    __shared__ __align__(16) uint32_t sAl[2][128 * 12];
    __shared__ __align__(16) uint32_t sBh[2][8 * 136];
    __shared__ __align__(16) uint32_t sBl[2][8 * 136];

    int tid = threadIdx.x;
    int lane = tid & 31, warp = tid >> 5;
    int g = lane >> 2, t4 = lane & 3;
    int wm = (warp >> 1) * 64, wn = (warp & 1) * 64;
    int bm = blockIdx.x * 128, bn = blockIdx.y * 128;

    float acc[4][8][4] = {};

    // cp.async chunk coordinates (2 chunks of 16B per thread per array)
    // A: 128 rows x 8 words: chunk c -> row c>>1, word (c&1)*4
    // B: 8 kp-rows x 128 words: chunk c -> kp c>>5, n0 (c&31)*4
    int ar0 = tid >> 1, aw0 = (tid & 1) * 4;
    int ar1 = 64 + ar0, aw1 = aw0;
    int bkp0 = tid >> 5, bn0 = (tid & 31) * 4;         // tid 0..127 -> kp 0..3
    int bkp1 = 4 + bkp0, bn1 = bn0;                    // kp 4..7
    int agr0 = bm + ar0; if (agr0 > M - 1) agr0 = M - 1;
    int agr1 = bm + ar1; if (agr1 > M - 1) agr1 = M - 1;
    int xrow = bm + tid; if (xrow > M - 1) xrow = M - 1;   // layer-0: row per thread

    uint32_t sAh_b = (uint32_t)__cvta_generic_to_shared(&sAh[0][0]);
    uint32_t sAl_b = (uint32_t)__cvta_generic_to_shared(&sAl[0][0]);
    uint32_t sBh_b = (uint32_t)__cvta_generic_to_shared(&sBh[0][0]);
    uint32_t sBl_b = (uint32_t)__cvta_generic_to_shared(&sBl[0][0]);
    const uint32_t ABUF = 128 * 12 * 4, BBUF = 8 * 136 * 4;

    // ldmatrix per-lane offset within an m16k16 A block (rows lane&15, words (lane>>4)*4)
    uint32_t lds_off = (uint32_t)(((lane & 15) * 12 + (lane >> 4) * 4) * 4);

    float xr[16];  // layer-0 raw fp32 row chunk (floats 2p..2p+15)

    auto issueB = [&](int st, int k0) {
        int p = k0 >> 1;
        uint32_t d0 = sBh_b + st * BBUF + (bkp0 * 136 + bn0) * 4;
        uint32_t d1 = sBh_b + st * BBUF + (bkp1 * 136 + bn1) * 4;
        CP_ASYNC16(d0, Bh + (long)(p + bkp0) * 256 + bn + bn0);
        CP_ASYNC16(d1, Bh + (long)(p + bkp1) * 256 + bn + bn1);
        uint32_t e0 = sBl_b + st * BBUF + (bkp0 * 136 + bn0) * 4;
        uint32_t e1 = sBl_b + st * BBUF + (bkp1 * 136 + bn1) * 4;
        CP_ASYNC16(e0, Bl + (long)(p + bkp0) * 256 + bn + bn0);
        CP_ASYNC16(e1, Bl + (long)(p + bkp1) * 256 + bn + bn1);
    };
    auto issueA1 = [&](int st, int k0) {   // layer-1: cp.async from pre-split
        int p = k0 >> 1;
        CP_ASYNC16(sAh_b + st * ABUF + (ar0 * 12 + aw0) * 4, g_ahi + (long)agr0 * 128 + p + aw0);
        CP_ASYNC16(sAh_b + st * ABUF + (ar1 * 12 + aw1) * 4, g_ahi + (long)agr1 * 128 + p + aw1);
        CP_ASYNC16(sAl_b + st * ABUF + (ar0 * 12 + aw0) * 4, g_alo + (long)agr0 * 128 + p + aw0);
        CP_ASYNC16(sAl_b + st * ABUF + (ar1 * 12 + aw1) * 4, g_alo + (long)agr1 * 128 + p + aw1);
    };
    auto gloadA0 = [&](int k0) {           // layer-0: fp32 regs
        const float* src = x + (long)xrow * 256 + k0;
#pragma unroll
        for (int i = 0; i < 4; i++) *(float4*)&xr[i * 4] = *(const float4*)(src + i * 4);
    };
    auto storeA0 = [&](int st) {           // layer-0: split + store
        uint32_t wh[8], wl[8];
#pragma unroll
        for (int w = 0; w < 8; w++) wh[w] = pack_split_h2(xr[2 * w], xr[2 * w + 1], wl[w]);
        *(uint4*)&sAh[st][tid * 12 + 0] = *(uint4*)&wh[0];
        *(uint4*)&sAh[st][tid * 12 + 4] = *(uint4*)&wh[4];
        *(uint4*)&sAl[st][tid * 12 + 0] = *(uint4*)&wl[0];
        *(uint4*)&sAl[st][tid * 12 + 4] = *(uint4*)&wl[4];
    };

    // prologue: tile 0
    if (LAYER == 0) {
        gloadA0(0);
        issueB(0, 0);
        CP_COMMIT();
        storeA0(0);
        gloadA0(16);
    } else {
        issueA1(0, 0);
        issueB(0, 0);
        CP_COMMIT();
    }

#pragma unroll 1
    for (int it = 0; it < 16; it++) {
        int cb = it & 1;
        CP_WAIT0();
        __syncthreads();
        if (it < 15) {
            issueB(cb ^ 1, (it + 1) * 16);
            if (LAYER == 0) {
                CP_COMMIT();
                storeA0(cb ^ 1);           // regs hold tile it+1
                if (it < 14) gloadA0((it + 2) * 16);
            } else {
                issueA1(cb ^ 1, (it + 1) * 16);
                CP_COMMIT();
            }
        }
        // ---- compute tile it ----
        uint32_t ah[4][4], al[4][4];
#pragma unroll
        for (int mi = 0; mi < 4; mi++) {
            uint32_t base = (uint32_t)((wm + mi * 16) * 48) + lds_off;
            ldsm4(ah[mi], sAh_b + cb * ABUF + base);
            ldsm4(al[mi], sAl_b + cb * ABUF + base);
        }
#pragma unroll
        for (int ni = 0; ni < 8; ni++) {
            int cidx = wn + ni * 8 + g;
            uint32_t bh0 = sBh[cb][t4 * 136 + cidx];
            uint32_t bh1 = sBh[cb][(4 + t4) * 136 + cidx];
            uint32_t bl0 = sBl[cb][t4 * 136 + cidx];
            uint32_t bl1 = sBl[cb][(4 + t4) * 136 + cidx];
#pragma unroll
            for (int mi = 0; mi < 4; mi++) {
                MMA_F16(acc[mi][ni], ah[mi], bh0, bh1);
                MMA_F16(acc[mi][ni], ah[mi], bl0, bl1);
                MMA_F16(acc[mi][ni], al[mi], bh0, bh1);
            }
        }
    }

    // ---- epilogue: fp16 feature store + fused alpha partials ----
    int head = (H == 1) ? 0 : (bn + wn) / (CF / H);  // warp's 64 cols lie in one head (H=4)
#pragma unroll
    for (int mi = 0; mi < 4; mi++) {
        int r = bm + wm + mi * 16 + g;
        float sA = 0, dA = 0, sB = 0, dB = 0;
#pragma unroll
        for (int ni = 0; ni < 8; ni++) {
            int cc = bn + wn + ni * 8 + 2 * t4;
            int wd = cc >> 1;
            float c0 = __ldg(&a_s[cc]), c1 = __ldg(&a_s[cc + 1]);
            float d0 = __ldg(&a_d[cc]), d1 = __ldg(&a_d[cc + 1]);
            sA += acc[mi][ni][0] * c0 + acc[mi][ni][1] * c1;
            dA += acc[mi][ni][0] * d0 + acc[mi][ni][1] * d1;
            sB += acc[mi][ni][2] * c0 + acc[mi][ni][3] * c1;
            dB += acc[mi][ni][2] * d0 + acc[mi][ni][3] * d1;
            if (r < M) {
                __half2 p = __floats2half2_rn(acc[mi][ni][0], acc[mi][ni][1]);
                g_hf16[(long)r * 128 + wd] = *reinterpret_cast<uint32_t*>(&p);
            }
            if (r + 8 < M) {
                __half2 p = __floats2half2_rn(acc[mi][ni][2], acc[mi][ni][3]);
                g_hf16[(long)(r + 8) * 128 + wd] = *reinterpret_cast<uint32_t*>(&p);
            }
        }
        sA += __shfl_xor_sync(0xffffffffu, sA, 1); sA += __shfl_xor_sync(0xffffffffu, sA, 2);
        dA += __shfl_xor_sync(0xffffffffu, dA, 1); dA += __shfl_xor_sync(0xffffffffu, dA, 2);
        sB += __shfl_xor_sync(0xffffffffu, sB, 1); sB += __shfl_xor_sync(0xffffffffu, sB, 2);
        dB += __shfl_xor_sync(0xffffffffu, dB, 1); dB += __shfl_xor_sync(0xffffffffu, dB, 2);
        if (t4 == 0) {
            if (r < M) {
                atomicAdd(&asrc[r * H + head], sA);
                atomicAdd(&adst[r * H + head], dA);
            }
            if (r + 8 < M) {
                atomicAdd(&asrc[(r + 8) * H + head], sB);
                atomicAdd(&adst[(r + 8) * H + head], dB);
            }
        }
    }
}

// ---------------- fused softmax-attention aggregation: warp per dst node ----------------
template <int H, int CH, bool ELU_ACT, bool SPLIT, int LYR>
__global__ void agg_kernel(const float* __restrict__ bias, float* __restrict__ out) {
    int node = blockIdx.x * 8 + (threadIdx.x >> 5);
    if (node >= NN) return;
    int lane = threadIdx.x & 31;
    int head = (lane * 8) / CH;
    const float* asrc = (LYR == 0) ? g_asrc : g_asrc2;
    const float* adstp = (LYR == 0) ? g_adst : g_adst2;
    float ad = adstp[node * H + head];
    const uint4* hb = (const uint4*)g_hf16;
    float a0 = 0, a1 = 0, a2 = 0, a3 = 0, a4 = 0, a5 = 0, a6 = 0, a7 = 0;
    float denom = 0.f;
    int j0 = g_rowptr[node], j1 = g_rowptr[node + 1];

    auto accum = [&](uint4 pk, float w) {
        float2 f0 = __half22float2(*reinterpret_cast<__half2*>(&pk.x));
        float2 f1 = __half22float2(*reinterpret_cast<__half2*>(&pk.y));
        float2 f2 = __half22float2(*reinterpret_cast<__half2*>(&pk.z));
        float2 f3 = __half22float2(*reinterpret_cast<__half2*>(&pk.w));
        a0 += w * f0.x; a1 += w * f0.y; a2 += w * f1.x; a3 += w * f1.y;
        a4 += w * f2.x; a5 += w * f2.y; a6 += w * f3.x; a7 += w * f3.y;
    };
    auto mkw = [&](float e) {
        e += ad;
        e = (e > 0.f) ? e : 0.2f * e;
        return __expf(e);
    };

    int j = j0;
    for (; j + 4 <= j1; j += 4) {
        int s0 = __ldg(&g_colsrc[j]);
        int s1 = __ldg(&g_colsrc[j + 1]);
        int s2 = __ldg(&g_colsrc[j + 2]);
        int s3 = __ldg(&g_colsrc[j + 3]);
        float e0 = __ldg(&asrc[s0 * H + head]);
        float e1 = __ldg(&asrc[s1 * H + head]);
        float e2 = __ldg(&asrc[s2 * H + head]);
        float e3 = __ldg(&asrc[s3 * H + head]);
        uint4 p0 = __ldg(&hb[(long)s0 * 32 + lane]);
        uint4 p1 = __ldg(&hb[(long)s1 * 32 + lane]);
        uint4 p2 = __ldg(&hb[(long)s2 * 32 + lane]);
        uint4 p3 = __ldg(&hb[(long)s3 * 32 + lane]);
        float w0 = mkw(e0), w1 = mkw(e1), w2 = mkw(e2), w3 = mkw(e3);
        denom += (w0 + w1) + (w2 + w3);
        accum(p0, w0); accum(p1, w1); accum(p2, w2); accum(p3, w3);
    }
    for (; j < j1; j++) {
        int s = __ldg(&g_colsrc[j]);
        float w = mkw(__ldg(&asrc[s * H + head]));
        denom += w;
        accum(__ldg(&hb[(long)s * 32 + lane]), w);
    }

    float inv = 1.f / denom;
    const float4* bb = (const float4*)bias + lane * 2;
    float4 b0 = bb[0], b1 = bb[1];
    float r[8];
    r[0] = a0 * inv + b0.x; r[1] = a1 * inv + b0.y;
    r[2] = a2 * inv + b0.z; r[3] = a3 * inv + b0.w;
    r[4] = a4 * inv + b1.x; r[5] = a5 * inv + b1.y;
    r[6] = a6 * inv + b1.z; r[7] = a7 * inv + b1.w;
    if (ELU_ACT) {
#pragma unroll
        for (int k = 0; k < 8; k++) r[k] = (r[k] > 0.f) ? r[k] : expm1f(r[k]);
    }
    if (SPLIT) {
        uint32_t wh[4], wl[4];
#pragma unroll
        for (int p = 0; p < 4; p++) wh[p] = pack_split_h2(r[2 * p], r[2 * p + 1], wl[p]);
        long ob = (long)node * 128 + lane * 4;
        *(uint4*)&g_ahi[ob] = *(uint4*)wh;
        *(uint4*)&g_alo[ob] = *(uint4*)wl;
        if (lane == 0) {
            g_asrc2[node] = 0.f;
            g_adst2[node] = 0.f;
        }
    } else {
        long ob = (long)node * CF + lane * 8;
        *(float4*)&out[ob]     = make_float4(r[0], r[1], r[2], r[3]);
        *(float4*)&out[ob + 4] = make_float4(r[4], r[5], r[6], r[7]);
    }
}

// ---------------- launch: kernel launches ONLY (graph-capture safe) ----------------
extern "C" void kernel_launch(void* const* d_in, const int* in_sizes, int n_in,
                              void* d_out, int out_size) {
    const float* x    = (const float*)d_in[0];
    const int* ei32   = (const int*)d_in[1];
    const float* W1   = (const float*)d_in[2];
    const float* as1  = (const float*)d_in[3];
    const float* ad1  = (const float*)d_in[4];
    const float* b1   = (const float*)d_in[5];
    const float* W2   = (const float*)d_in[6];
    const float* as2  = (const float*)d_in[7];
    const float* ad2  = (const float*)d_in[8];
    const float* b2   = (const float*)d_in[9];
    float* out        = (float*)d_out;

    dim3 gg((NN + 127) / 128, 2);

    // order keeps gemm1 in the ncu capture window (position 4)
    zero_all_kernel<<<(NN + 255) / 256, 256>>>();
    split_w_kernel<0><<<(128 * 256 + 255) / 256, 256>>>(W1);
    split_w_kernel<1><<<(128 * 256 + 255) / 256, 256>>>(W2);
    gemmf16_kernel<0, 4><<<gg, 128>>>(NN, x, as1, ad1);

    detect_kernel<<<1, 32>>>(ei32);
    hist_kernel<<<(EETOT + 255) / 256, 256>>>(ei32);
    scan_kernel<<<1, 1024>>>();
    scatter_kernel<<<(EETOT + 255) / 256, 256>>>(ei32);

    agg_kernel<4, 64, true, true, 0><<<(NN + 7) / 8, 256>>>(b1, (float*)0);
    gemmf16_kernel<1, 1><<<gg, 128>>>(NN, (const float*)0, as2, ad2);
    agg_kernel<1, 256, false, false, 1><<<(NN + 7) / 8, 256>>>(b2, out);
}

// round 14
// speedup vs baseline: 1.3175x; 1.0285x over previous
#include <cuda_runtime.h>
#include <cuda_fp16.h>
#include <stdint.h>
#include <math.h>

#define NN 50000
#define EC 800000
#define EETOT 850000
#define CF 256

// ---------------- scratch (static __device__, no allocations) ----------------
__device__ __align__(256) uint32_t g_ahi[NN * 128];   // layer-2 A operand hi (packed half2 k-pairs)
__device__ __align__(256) uint32_t g_alo[NN * 128];   // layer-2 A operand lo
__device__ __align__(256) uint32_t g_w1h[256 * 128];  // W packed [n][k-pair]  (n-major!)
__device__ __align__(256) uint32_t g_w1l[256 * 128];
__device__ __align__(256) uint32_t g_w2h[256 * 128];
__device__ __align__(256) uint32_t g_w2l[256 * 128];
__device__ __align__(256) uint32_t g_hf16[NN * 128];  // features, packed half2 (only copy)
__device__ __align__(256) float g_asrc[NN * 4];       // layer-1 alpha partials (atomics)
__device__ __align__(256) float g_adst[NN * 4];
__device__ __align__(256) float g_asrc2[NN];          // layer-2 alpha partials (zeroed by agg1)
__device__ __align__(256) float g_adst2[NN];
__device__ int g_rowptr[NN + 1];
__device__ int g_cnt[NN];
__device__ int g_cur[NN];
__device__ int g_colsrc[EETOT];
__device__ int g_is64;

// ---------------- helpers ----------------
__device__ __forceinline__ uint32_t pack_split_h2(float v0, float v1, uint32_t& lo_out) {
    __half h0 = __float2half_rn(v0);
    __half l0 = __float2half_rn(v0 - __half2float(h0));
    __half h1 = __float2half_rn(v1);
    __half l1 = __float2half_rn(v1 - __half2float(h1));
    __half2 hh = __halves2half2(h0, h1);
    __half2 ll = __halves2half2(l0, l1);
    lo_out = *reinterpret_cast<uint32_t*>(&ll);
    return *reinterpret_cast<uint32_t*>(&hh);
}

#define MMA_F16(c, a, b0, b1)                                                          \
    asm volatile(                                                                      \
        "mma.sync.aligned.m16n8k16.row.col.f32.f16.f16.f32 "                           \
        "{%0,%1,%2,%3},{%4,%5,%6,%7},{%8,%9},{%0,%1,%2,%3};"                           \
        : "+f"(c[0]), "+f"(c[1]), "+f"(c[2]), "+f"(c[3])                               \
        : "r"(a[0]), "r"(a[1]), "r"(a[2]), "r"(a[3]), "r"(b0), "r"(b1))

__device__ __forceinline__ void ldsm4(uint32_t (&r)[4], uint32_t saddr) {
    asm volatile("ldmatrix.sync.aligned.m8n8.x4.shared.b16 {%0,%1,%2,%3}, [%4];"
                 : "=r"(r[0]), "=r"(r[1]), "=r"(r[2]), "=r"(r[3])
                 : "r"(saddr));
}

#define CP_ASYNC16(dst_u32, src_ptr)                                                   \
    asm volatile("cp.async.cg.shared.global [%0], [%1], 16;" ::"r"(dst_u32), "l"(src_ptr))
#define CP_COMMIT() asm volatile("cp.async.commit_group;")
#define CP_WAIT0()  asm volatile("cp.async.wait_group 0;")

__device__ __forceinline__ int edge_at(const int* __restrict__ ei32, long pos, int is64) {
    int v = is64 ? ei32[2 * pos] : ei32[pos];
    v = (v < 0) ? 0 : v;
    return (v >= NN) ? (NN - 1) : v;
}

// ---------------- edge dtype detection (warp-parallel) ----------------
__global__ void detect_kernel(const int* __restrict__ ei32) {
    int lane = threadIdx.x;
    int bad = 0;
    for (int k = lane; k < 64; k += 32)
        if (ei32[2 * k + 1] != 0) bad = 1;
    unsigned m = __ballot_sync(0xffffffffu, bad);
    if (lane == 0) g_is64 = (m == 0);
}

// ---------------- W split: fp16 hi/lo, n-major [n][kp] layout ----------------
template <int L>
__global__ void split_w_kernel(const float* __restrict__ W) {
    uint32_t* wh = (L == 0) ? g_w1h : g_w2h;
    uint32_t* wl = (L == 0) ? g_w1l : g_w2l;
    int i = blockIdx.x * 256 + threadIdx.x;
    if (i >= 256 * 128) return;
    int n = i >> 7, kp = i & 127;
    float v0 = W[(2 * kp) * 256 + n], v1 = W[(2 * kp + 1) * 256 + n];
    uint32_t lo;
    uint32_t hi = pack_split_h2(v0, v1, lo);
    wh[n * 128 + kp] = hi;   // writes coalesced (kp contiguous per n)
    wl[n * 128 + kp] = lo;
}

// ---------------- zero ----------------
__global__ void zero_all_kernel() {
    int i = blockIdx.x * 256 + threadIdx.x;
    if (i < NN) {
        g_cnt[i] = 0;
        g_cur[i] = 0;
        *(float4*)&g_asrc[i * 4] = make_float4(0.f, 0.f, 0.f, 0.f);
        *(float4*)&g_adst[i * 4] = make_float4(0.f, 0.f, 0.f, 0.f);
    }
}

// ---------------- CSR build ----------------
__global__ void hist_kernel(const int* __restrict__ ei32) {
    int i = blockIdx.x * 256 + threadIdx.x;
    if (i >= EETOT) return;
    int is64 = g_is64;
    int dst = (i < EC) ? edge_at(ei32, (long)EC + i, is64) : (i - EC);
    atomicAdd(&g_cnt[dst], 1);
}

__global__ void scan_kernel() {
    __shared__ int s[1024];
    int t = threadIdx.x;
    const int chunk = (NN + 1023) / 1024;
    int lo = t * chunk;
    int hi = lo + chunk; if (hi > NN) hi = NN;
    int sum = 0;
    for (int i = lo; i < hi; i++) sum += g_cnt[i];
    s[t] = sum;
    __syncthreads();
    for (int d = 1; d < 1024; d <<= 1) {
        int v = (t >= d) ? s[t - d] : 0;
        __syncthreads();
        s[t] += v;
        __syncthreads();
    }
    int run = s[t] - sum;
    for (int i = lo; i < hi; i++) { g_rowptr[i] = run; run += g_cnt[i]; }
    if (t == 0) g_rowptr[NN] = EETOT;
}

__global__ void scatter_kernel(const int* __restrict__ ei32) {
    int i = blockIdx.x * 256 + threadIdx.x;
    if (i >= EETOT) return;
    int is64 = g_is64;
    int src, dst;
    if (i < EC) {
        src = edge_at(ei32, i, is64);
        dst = edge_at(ei32, (long)EC + i, is64);
    } else {
        src = i - EC;
        dst = i - EC;
    }
    int pos = g_rowptr[dst] + atomicAdd(&g_cur[dst], 1);
    g_colsrc[pos] = src;
}

// ---------------- GEMM + fused alpha: h = A @ W (split-FP16, 3 products) ----------------
// CTA 128x128, 4 warps (2x2), warp tile 64x64. A AND B fragments via ldmatrix.x4.
// Tiles: 128 rows x 8 words, XOR-swizzled 16B chunks (chunk ^= (row>>2)&1) -> conflict-free.
// cp.async fills; one __syncthreads per K-tile. Smem 32KB.
// LAYER 0: A from fp32 x, split in-register. LAYER 1: A pre-split, cp.async.
template <int LAYER, int H>
__global__ void __launch_bounds__(128) gemmf16_kernel(
    int M, const float* __restrict__ x, const float* __restrict__ a_s,
    const float* __restrict__ a_d) {
    const uint32_t* __restrict__ Bh = (LAYER == 0) ? g_w1h : g_w2h;
    const uint32_t* __restrict__ Bl = (LAYER == 0) ? g_w1l : g_w2l;
    float* __restrict__ asrc = (LAYER == 0) ? g_asrc : g_asrc2;
    float* __restrict__ adst = (LAYER == 0) ? g_adst : g_adst2;

    __shared__ __align__(16) uint32_t sAh[2][128 * 8];
    __shared__ __align__(16) uint32_t sAl[2][128 * 8];
    __shared__ __align__(16) uint32_t sBh[2][128 * 8];
    __shared__ __align__(16) uint32_t sBl[2][128 * 8];

    int tid = threadIdx.x;
    int lane = tid & 31, warp = tid >> 5;
    int g = lane >> 2, t4 = lane & 3;
    int wm = (warp >> 1) * 64, wn = (warp & 1) * 64;
    int bm = blockIdx.x * 128, bn = blockIdx.y * 128;

    float acc[4][8][4] = {};

    // cp.async coords: thread -> rows (tid>>1, 64+(tid>>1)), logical chunk tid&1
    int ar = tid >> 1, ac = tid & 1;
    int pc = ac ^ ((ar >> 2) & 1);        // physical chunk (same for row ar and 64+ar)
    int agr0 = bm + ar;       if (agr0 > M - 1) agr0 = M - 1;
    int agr1 = bm + 64 + ar;  if (agr1 > M - 1) agr1 = M - 1;
    int xrow = bm + tid;      if (xrow > M - 1) xrow = M - 1;   // layer-0: row per thread
    int swt = (tid >> 2) & 1;                                    // layer-0 store swizzle

    uint32_t sAh_b = (uint32_t)__cvta_generic_to_shared(&sAh[0][0]);
    uint32_t sAl_b = (uint32_t)__cvta_generic_to_shared(&sAl[0][0]);
    uint32_t sBh_b = (uint32_t)__cvta_generic_to_shared(&sBh[0][0]);
    uint32_t sBl_b = (uint32_t)__cvta_generic_to_shared(&sBl[0][0]);
    const uint32_t BUF = 128 * 8 * 4;

    // per-lane ldmatrix offsets (swizzle bit folds into lane constants)
    uint32_t lds_offA =
        (uint32_t)(((lane & 15) * 8 + (((lane >> 4) ^ ((lane >> 2) & 1)) << 2)) * 4);
    uint32_t lds_offB =
        (uint32_t)((((lane >> 4) * 8 + (lane & 7)) * 8 +
                    ((((lane >> 3) & 1) ^ ((lane >> 2) & 1)) << 2)) * 4);

    float xr[16];  // layer-0 raw fp32 row chunk

    auto issueB = [&](int st, int k0) {
        int p = k0 >> 1;
        uint32_t o0 = (uint32_t)((ar * 8 + pc * 4) * 4);
        uint32_t o1 = (uint32_t)(((64 + ar) * 8 + pc * 4) * 4);
        const uint32_t* s0 = Bh + (long)(bn + ar) * 128 + p + ac * 4;
        const uint32_t* s1 = Bh + (long)(bn + 64 + ar) * 128 + p + ac * 4;
        CP_ASYNC16(sBh_b + st * BUF + o0, s0);
        CP_ASYNC16(sBh_b + st * BUF + o1, s1);
        const uint32_t* t0 = Bl + (long)(bn + ar) * 128 + p + ac * 4;
        const uint32_t* t1 = Bl + (long)(bn + 64 + ar) * 128 + p + ac * 4;
        CP_ASYNC16(sBl_b + st * BUF + o0, t0);
        CP_ASYNC16(sBl_b + st * BUF + o1, t1);
    };
    auto issueA1 = [&](int st, int k0) {
        int p = k0 >> 1;
        uint32_t o0 = (uint32_t)((ar * 8 + pc * 4) * 4);
        uint32_t o1 = (uint32_t)(((64 + ar) * 8 + pc * 4) * 4);
        CP_ASYNC16(sAh_b + st * BUF + o0, g_ahi + (long)agr0 * 128 + p + ac * 4);
        CP_ASYNC16(sAh_b + st * BUF + o1, g_ahi + (long)agr1 * 128 + p + ac * 4);
        CP_ASYNC16(sAl_b + st * BUF + o0, g_alo + (long)agr0 * 128 + p + ac * 4);
        CP_ASYNC16(sAl_b + st * BUF + o1, g_alo + (long)agr1 * 128 + p + ac * 4);
    };
    auto gloadA0 = [&](int k0) {
        const float* src = x + (long)xrow * 256 + k0;
#pragma unroll
        for (int i = 0; i < 4; i++) *(float4*)&xr[i * 4] = *(const float4*)(src + i * 4);
    };
    auto storeA0 = [&](int st) {
        uint32_t wh[8], wl[8];
#pragma unroll
        for (int w = 0; w < 8; w++) wh[w] = pack_split_h2(xr[2 * w], xr[2 * w + 1], wl[w]);
        *(uint4*)&sAh[st][tid * 8 + swt * 4]       = *(uint4*)&wh[0];
        *(uint4*)&sAh[st][tid * 8 + (swt ^ 1) * 4] = *(uint4*)&wh[4];
        *(uint4*)&sAl[st][tid * 8 + swt * 4]       = *(uint4*)&wl[0];
        *(uint4*)&sAl[st][tid * 8 + (swt ^ 1) * 4] = *(uint4*)&wl[4];
    };

    // prologue: tile 0
    if (LAYER == 0) {
        gloadA0(0);
        issueB(0, 0);
        CP_COMMIT();
        storeA0(0);
        gloadA0(16);
    } else {
        issueA1(0, 0);
        issueB(0, 0);
        CP_COMMIT();
    }

#pragma unroll 1
    for (int it = 0; it < 16; it++) {
        int cb = it & 1;
        CP_WAIT0();
        __syncthreads();
        if (it < 15) {
            issueB(cb ^ 1, (it + 1) * 16);
            if (LAYER == 0) {
                CP_COMMIT();
                storeA0(cb ^ 1);           // regs hold tile it+1
                if (it < 14) gloadA0((it + 2) * 16);
            } else {
                issueA1(cb ^ 1, (it + 1) * 16);
                CP_COMMIT();
            }
        }
        // ---- compute tile it ----
        uint32_t ah[4][4], al[4][4];
#pragma unroll
        for (int mi = 0; mi < 4; mi++) {
            uint32_t base = (uint32_t)((wm + mi * 16) * 32);
            ldsm4(ah[mi], sAh_b + cb * BUF + base + lds_offA);
            ldsm4(al[mi], sAl_b + cb * BUF + base + lds_offA);
        }
#pragma unroll
        for (int nip = 0; nip < 4; nip++) {
            uint32_t bh[4], bl[4];
            uint32_t base = (uint32_t)((wn + nip * 16) * 32);
            ldsm4(bh, sBh_b + cb * BUF + base + lds_offB);
            ldsm4(bl, sBl_b + cb * BUF + base + lds_offB);
#pragma unroll
            for (int mi = 0; mi < 4; mi++) {
                MMA_F16(acc[mi][2 * nip],     ah[mi], bh[0], bh[1]);
                MMA_F16(acc[mi][2 * nip],     ah[mi], bl[0], bl[1]);
                MMA_F16(acc[mi][2 * nip],     al[mi], bh[0], bh[1]);
                MMA_F16(acc[mi][2 * nip + 1], ah[mi], bh[2], bh[3]);
                MMA_F16(acc[mi][2 * nip + 1], ah[mi], bl[2], bl[3]);
                MMA_F16(acc[mi][2 * nip + 1], al[mi], bh[2], bh[3]);
            }
        }
    }

    // ---- epilogue: fp16 feature store + fused alpha partials ----
    int head = (H == 1) ? 0 : (bn + wn) / (CF / H);  // warp's 64 cols lie in one head (H=4)
#pragma unroll
    for (int mi = 0; mi < 4; mi++) {
        int r = bm + wm + mi * 16 + g;
        float sA = 0, dA = 0, sB = 0, dB = 0;
#pragma unroll
        for (int ni = 0; ni < 8; ni++) {
            int cc = bn + wn + ni * 8 + 2 * t4;
            int wd = cc >> 1;
            float c0 = __ldg(&a_s[cc]), c1 = __ldg(&a_s[cc + 1]);
            float d0 = __ldg(&a_d[cc]), d1 = __ldg(&a_d[cc + 1]);
            sA += acc[mi][ni][0] * c0 + acc[mi][ni][1] * c1;
            dA += acc[mi][ni][0] * d0 + acc[mi][ni][1] * d1;
            sB += acc[mi][ni][2] * c0 + acc[mi][ni][3] * c1;
            dB += acc[mi][ni][2] * d0 + acc[mi][ni][3] * d1;
            if (r < M) {
                __half2 p = __floats2half2_rn(acc[mi][ni][0], acc[mi][ni][1]);
                g_hf16[(long)r * 128 + wd] = *reinterpret_cast<uint32_t*>(&p);
            }
            if (r + 8 < M) {
                __half2 p = __floats2half2_rn(acc[mi][ni][2], acc[mi][ni][3]);
                g_hf16[(long)(r + 8) * 128 + wd] = *reinterpret_cast<uint32_t*>(&p);
            }
        }
        sA += __shfl_xor_sync(0xffffffffu, sA, 1); sA += __shfl_xor_sync(0xffffffffu, sA, 2);
        dA += __shfl_xor_sync(0xffffffffu, dA, 1); dA += __shfl_xor_sync(0xffffffffu, dA, 2);
        sB += __shfl_xor_sync(0xffffffffu, sB, 1); sB += __shfl_xor_sync(0xffffffffu, sB, 2);
        dB += __shfl_xor_sync(0xffffffffu, dB, 1); dB += __shfl_xor_sync(0xffffffffu, dB, 2);
        if (t4 == 0) {
            if (r < M) {
                atomicAdd(&asrc[r * H + head], sA);
                atomicAdd(&adst[r * H + head], dA);
            }
            if (r + 8 < M) {
                atomicAdd(&asrc[(r + 8) * H + head], sB);
                atomicAdd(&adst[(r + 8) * H + head], dB);
            }
        }
    }
}

// ---------------- fused softmax-attention aggregation: warp per dst node ----------------
template <int H, int CH, bool ELU_ACT, bool SPLIT, int LYR>
__global__ void agg_kernel(const float* __restrict__ bias, float* __restrict__ out) {
    int node = blockIdx.x * 8 + (threadIdx.x >> 5);
    if (node >= NN) return;
    int lane = threadIdx.x & 31;
    int head = (lane * 8) / CH;
    const float* asrc = (LYR == 0) ? g_asrc : g_asrc2;
    const float* adstp = (LYR == 0) ? g_adst : g_adst2;
    float ad = adstp[node * H + head];
    const uint4* hb = (const uint4*)g_hf16;
    float a0 = 0, a1 = 0, a2 = 0, a3 = 0, a4 = 0, a5 = 0, a6 = 0, a7 = 0;
    float denom = 0.f;
    int j0 = g_rowptr[node], j1 = g_rowptr[node + 1];

    auto accum = [&](uint4 pk, float w) {
        float2 f0 = __half22float2(*reinterpret_cast<__half2*>(&pk.x));
        float2 f1 = __half22float2(*reinterpret_cast<__half2*>(&pk.y));
        float2 f2 = __half22float2(*reinterpret_cast<__half2*>(&pk.z));
        float2 f3 = __half22float2(*reinterpret_cast<__half2*>(&pk.w));
        a0 += w * f0.x; a1 += w * f0.y; a2 += w * f1.x; a3 += w * f1.y;
        a4 += w * f2.x; a5 += w * f2.y; a6 += w * f3.x; a7 += w * f3.y;
    };
    auto mkw = [&](float e) {
        e += ad;
        e = (e > 0.f) ? e : 0.2f * e;
        return __expf(e);
    };

    int j = j0;
    for (; j + 4 <= j1; j += 4) {
        int s0 = __ldg(&g_colsrc[j]);
        int s1 = __ldg(&g_colsrc[j + 1]);
        int s2 = __ldg(&g_colsrc[j + 2]);
        int s3 = __ldg(&g_colsrc[j + 3]);
        float e0 = __ldg(&asrc[s0 * H + head]);
        float e1 = __ldg(&asrc[s1 * H + head]);
        float e2 = __ldg(&asrc[s2 * H + head]);
        float e3 = __ldg(&asrc[s3 * H + head]);
        uint4 p0 = __ldg(&hb[(long)s0 * 32 + lane]);
        uint4 p1 = __ldg(&hb[(long)s1 * 32 + lane]);
        uint4 p2 = __ldg(&hb[(long)s2 * 32 + lane]);
        uint4 p3 = __ldg(&hb[(long)s3 * 32 + lane]);
        float w0 = mkw(e0), w1 = mkw(e1), w2 = mkw(e2), w3 = mkw(e3);
        denom += (w0 + w1) + (w2 + w3);
        accum(p0, w0); accum(p1, w1); accum(p2, w2); accum(p3, w3);
    }
    for (; j < j1; j++) {
        int s = __ldg(&g_colsrc[j]);
        float w = mkw(__ldg(&asrc[s * H + head]));
        denom += w;
        accum(__ldg(&hb[(long)s * 32 + lane]), w);
    }

    float inv = 1.f / denom;
    const float4* bb = (const float4*)bias + lane * 2;
    float4 b0 = bb[0], b1 = bb[1];
    float r[8];
    r[0] = a0 * inv + b0.x; r[1] = a1 * inv + b0.y;
    r[2] = a2 * inv + b0.z; r[3] = a3 * inv + b0.w;
    r[4] = a4 * inv + b1.x; r[5] = a5 * inv + b1.y;
    r[6] = a6 * inv + b1.z; r[7] = a7 * inv + b1.w;
    if (ELU_ACT) {
#pragma unroll
        for (int k = 0; k < 8; k++) r[k] = (r[k] > 0.f) ? r[k] : expm1f(r[k]);
    }
    if (SPLIT) {
        uint32_t wh[4], wl[4];
#pragma unroll
        for (int p = 0; p < 4; p++) wh[p] = pack_split_h2(r[2 * p], r[2 * p + 1], wl[p]);
        long ob = (long)node * 128 + lane * 4;
        *(uint4*)&g_ahi[ob] = *(uint4*)wh;
        *(uint4*)&g_alo[ob] = *(uint4*)wl;
        if (lane == 0) {
            g_asrc2[node] = 0.f;
            g_adst2[node] = 0.f;
        }
    } else {
        long ob = (long)node * CF + lane * 8;
        *(float4*)&out[ob]     = make_float4(r[0], r[1], r[2], r[3]);
        *(float4*)&out[ob + 4] = make_float4(r[4], r[5], r[6], r[7]);
    }
}

// ---------------- launch: kernel launches ONLY (graph-capture safe) ----------------
extern "C" void kernel_launch(void* const* d_in, const int* in_sizes, int n_in,
                              void* d_out, int out_size) {
    const float* x    = (const float*)d_in[0];
    const int* ei32   = (const int*)d_in[1];
    const float* W1   = (const float*)d_in[2];
    const float* as1  = (const float*)d_in[3];
    const float* ad1  = (const float*)d_in[4];
    const float* b1   = (const float*)d_in[5];
    const float* W2   = (const float*)d_in[6];
    const float* as2  = (const float*)d_in[7];
    const float* ad2  = (const float*)d_in[8];
    const float* b2   = (const float*)d_in[9];
    float* out        = (float*)d_out;

    dim3 gg((NN + 127) / 128, 2);

    // order keeps gemm1 in the ncu capture window (position 4)
    zero_all_kernel<<<(NN + 255) / 256, 256>>>();
    split_w_kernel<0><<<(256 * 128 + 255) / 256, 256>>>(W1);
    split_w_kernel<1><<<(256 * 128 + 255) / 256, 256>>>(W2);
    gemmf16_kernel<0, 4><<<gg, 128>>>(NN, x, as1, ad1);

    detect_kernel<<<1, 32>>>(ei32);
    hist_kernel<<<(EETOT + 255) / 256, 256>>>(ei32);
    scan_kernel<<<1, 1024>>>();
    scatter_kernel<<<(EETOT + 255) / 256, 256>>>(ei32);

    agg_kernel<4, 64, true, true, 0><<<(NN + 7) / 8, 256>>>(b1, (float*)0);
    gemmf16_kernel<1, 1><<<gg, 128>>>(NN, (const float*)0, as2, ad2);
    agg_kernel<1, 256, false, false, 1><<<(NN + 7) / 8, 256>>>(b2, out);
}

// round 16
// speedup vs baseline: 1.3894x; 1.0546x over previous
#include <cuda_runtime.h>
#include <cuda_fp16.h>
#include <stdint.h>
#include <math.h>

#define NN 50000
#define EC 800000
#define EETOT 850000
#define CF 256

// ---------------- scratch (static __device__, no allocations) ----------------
__device__ __align__(256) uint32_t g_ah[NN * 128];    // A operand fp16 (packed half2 k-pairs)
__device__ __align__(256) uint32_t g_w1h[256 * 128];  // W packed [n][k-pair] (n-major) hi
__device__ __align__(256) uint32_t g_w1l[256 * 128];  //                                lo
__device__ __align__(256) uint32_t g_w2h[256 * 128];
__device__ __align__(256) uint32_t g_w2l[256 * 128];
__device__ __align__(256) uint32_t g_hf16[NN * 128];  // features, packed half2 (only copy)
__device__ __align__(256) float g_asrc[NN * 4];       // layer-1 alpha partials (atomics)
__device__ __align__(256) float g_adst[NN * 4];
__device__ __align__(256) float g_asrc2[NN];          // layer-2 alpha partials (zeroed by agg1)
__device__ __align__(256) float g_adst2[NN];
__device__ int g_rowptr[NN + 1];
__device__ int g_cnt[NN];
__device__ int g_cur[NN];
__device__ int g_colsrc[EETOT];
__device__ int g_is64;

// ---------------- helpers ----------------
__device__ __forceinline__ uint32_t pack_split_h2(float v0, float v1, uint32_t& lo_out) {
    __half h0 = __float2half_rn(v0);
    __half l0 = __float2half_rn(v0 - __half2float(h0));
    __half h1 = __float2half_rn(v1);
    __half l1 = __float2half_rn(v1 - __half2float(h1));
    __half2 hh = __halves2half2(h0, h1);
    __half2 ll = __halves2half2(l0, l1);
    lo_out = *reinterpret_cast<uint32_t*>(&ll);
    return *reinterpret_cast<uint32_t*>(&hh);
}

#define MMA_F16(c, a, b0, b1)                                                          \
    asm volatile(                                                                      \
        "mma.sync.aligned.m16n8k16.row.col.f32.f16.f16.f32 "                           \
        "{%0,%1,%2,%3},{%4,%5,%6,%7},{%8,%9},{%0,%1,%2,%3};"                           \
        : "+f"(c[0]), "+f"(c[1]), "+f"(c[2]), "+f"(c[3])                               \
        : "r"(a[0]), "r"(a[1]), "r"(a[2]), "r"(a[3]), "r"(b0), "r"(b1))

__device__ __forceinline__ void ldsm4(uint32_t (&r)[4], uint32_t saddr) {
    asm volatile("ldmatrix.sync.aligned.m8n8.x4.shared.b16 {%0,%1,%2,%3}, [%4];"
                 : "=r"(r[0]), "=r"(r[1]), "=r"(r[2]), "=r"(r[3])
                 : "r"(saddr));
}

#define CP_ASYNC16(dst_u32, src_ptr)                                                   \
    asm volatile("cp.async.cg.shared.global [%0], [%1], 16;" ::"r"(dst_u32), "l"(src_ptr))
#define CP_COMMIT() asm volatile("cp.async.commit_group;")
#define CP_WAIT0()  asm volatile("cp.async.wait_group 0;")

__device__ __forceinline__ int edge_at(const int* __restrict__ ei32, long pos, int is64) {
    int v = is64 ? ei32[2 * pos] : ei32[pos];
    v = (v < 0) ? 0 : v;
    return (v >= NN) ? (NN - 1) : v;
}

// ---------------- edge dtype detection (warp-parallel) ----------------
__global__ void detect_kernel(const int* __restrict__ ei32) {
    int lane = threadIdx.x;
    int bad = 0;
    for (int k = lane; k < 64; k += 32)
        if (ei32[2 * k + 1] != 0) bad = 1;
    unsigned m = __ballot_sync(0xffffffffu, bad);
    if (lane == 0) g_is64 = (m == 0);
}

// ---------------- W split: fp16 hi/lo, n-major [n][kp] layout ----------------
template <int L>
__global__ void split_w_kernel(const float* __restrict__ W) {
    uint32_t* wh = (L == 0) ? g_w1h : g_w2h;
    uint32_t* wl = (L == 0) ? g_w1l : g_w2l;
    int i = blockIdx.x * 256 + threadIdx.x;
    if (i >= 256 * 128) return;
    int n = i >> 7, kp = i & 127;
    float v0 = W[(2 * kp) * 256 + n], v1 = W[(2 * kp + 1) * 256 + n];
    uint32_t lo;
    uint32_t hi = pack_split_h2(v0, v1, lo);
    wh[n * 128 + kp] = hi;
    wl[n * 128 + kp] = lo;
}

// ---------------- zero ----------------
__global__ void zero_all_kernel() {
    int i = blockIdx.x * 256 + threadIdx.x;
    if (i < NN) {
        g_cnt[i] = 0;
        g_cur[i] = 0;
        *(float4*)&g_asrc[i * 4] = make_float4(0.f, 0.f, 0.f, 0.f);
        *(float4*)&g_adst[i * 4] = make_float4(0.f, 0.f, 0.f, 0.f);
    }
}

// ---------------- CSR build ----------------
__global__ void hist_kernel(const int* __restrict__ ei32) {
    int i = blockIdx.x * 256 + threadIdx.x;
    if (i >= EETOT) return;
    int is64 = g_is64;
    int dst = (i < EC) ? edge_at(ei32, (long)EC + i, is64) : (i - EC);
    atomicAdd(&g_cnt[dst], 1);
}

__global__ void scan_kernel() {
    __shared__ int s[1024];
    int t = threadIdx.x;
    const int chunk = (NN + 1023) / 1024;
    int lo = t * chunk;
    int hi = lo + chunk; if (hi > NN) hi = NN;
    int sum = 0;
    for (int i = lo; i < hi; i++) sum += g_cnt[i];
    s[t] = sum;
    __syncthreads();
    for (int d = 1; d < 1024; d <<= 1) {
        int v = (t >= d) ? s[t - d] : 0;
        __syncthreads();
        s[t] += v;
        __syncthreads();
    }
    int run = s[t] - sum;
    for (int i = lo; i < hi; i++) { g_rowptr[i] = run; run += g_cnt[i]; }
    if (t == 0) g_rowptr[NN] = EETOT;
}

__global__ void scatter_kernel(const int* __restrict__ ei32) {
    int i = blockIdx.x * 256 + threadIdx.x;
    if (i >= EETOT) return;
    int is64 = g_is64;
    int src, dst;
    if (i < EC) {
        src = edge_at(ei32, i, is64);
        dst = edge_at(ei32, (long)EC + i, is64);
    } else {
        src = i - EC;
        dst = i - EC;
    }
    int pos = g_rowptr[dst] + atomicAdd(&g_cur[dst], 1);
    g_colsrc[pos] = src;
}

// ---------------- GEMM + fused alpha: h = A @ W, 2-product split-fp16 ----------------
// C = Ah*(Bh+Bl): A single fp16 (error Al*B ~ 2^-12 rel), W split hi/lo.
// CTA 128x128, 4 warps (2x2), warp tile 64x64. A+B fragments via ldmatrix.x4.
// Tiles: 128 rows x 8 words, XOR-swizzled 16B chunks (chunk ^= (row>>2)&1).
// cp.async fills; one __syncthreads per K-tile. Smem 24KB.
// LAYER 0: A from fp32 x, converted in-register. LAYER 1: A = g_ah, cp.async.
template <int LAYER, int H>
__global__ void __launch_bounds__(128) gemmf16_kernel(
    int M, const float* __restrict__ x, const float* __restrict__ a_s,
    const float* __restrict__ a_d) {
    const uint32_t* __restrict__ Bh = (LAYER == 0) ? g_w1h : g_w2h;
    const uint32_t* __restrict__ Bl = (LAYER == 0) ? g_w1l : g_w2l;
    float* __restrict__ asrc = (LAYER == 0) ? g_asrc : g_asrc2;
    float* __restrict__ adst = (LAYER == 0) ? g_adst : g_adst2;

    __shared__ __align__(16) uint32_t sAh[2][128 * 8];
    __shared__ __align__(16) uint32_t sBh[2][128 * 8];
    __shared__ __align__(16) uint32_t sBl[2][128 * 8];

    int tid = threadIdx.x;
    int lane = tid & 31, warp = tid >> 5;
    int g = lane >> 2, t4 = lane & 3;
    int wm = (warp >> 1) * 64, wn = (warp & 1) * 64;
    int bm = blockIdx.x * 128, bn = blockIdx.y * 128;

    float acc[4][8][4] = {};

    // cp.async coords: thread -> rows (tid>>1, 64+(tid>>1)), logical chunk tid&1
    int ar = tid >> 1, ac = tid & 1;
    int pc = ac ^ ((ar >> 2) & 1);        // physical chunk (same for row ar and 64+ar)
    int agr0 = bm + ar;       if (agr0 > M - 1) agr0 = M - 1;
    int agr1 = bm + 64 + ar;  if (agr1 > M - 1) agr1 = M - 1;
    int xrow = bm + tid;      if (xrow > M - 1) xrow = M - 1;   // layer-0: row per thread
    int swt = (tid >> 2) & 1;                                    // layer-0 store swizzle

    uint32_t sAh_b = (uint32_t)__cvta_generic_to_shared(&sAh[0][0]);
    uint32_t sBh_b = (uint32_t)__cvta_generic_to_shared(&sBh[0][0]);
    uint32_t sBl_b = (uint32_t)__cvta_generic_to_shared(&sBl[0][0]);
    const uint32_t BUF = 128 * 8 * 4;

    // per-lane ldmatrix offsets (swizzle bit folds into lane constants)
    uint32_t lds_offA =
        (uint32_t)(((lane & 15) * 8 + (((lane >> 4) ^ ((lane >> 2) & 1)) << 2)) * 4);
    uint32_t lds_offB =
        (uint32_t)((((lane >> 4) * 8 + (lane & 7)) * 8 +
                    ((((lane >> 3) & 1) ^ ((lane >> 2) & 1)) << 2)) * 4);

    float xr[16];  // layer-0 raw fp32 row chunk

    auto issueB = [&](int st, int k0) {
        int p = k0 >> 1;
        uint32_t o0 = (uint32_t)((ar * 8 + pc * 4) * 4);
        uint32_t o1 = (uint32_t)(((64 + ar) * 8 + pc * 4) * 4);
        CP_ASYNC16(sBh_b + st * BUF + o0, Bh + (long)(bn + ar) * 128 + p + ac * 4);
        CP_ASYNC16(sBh_b + st * BUF + o1, Bh + (long)(bn + 64 + ar) * 128 + p + ac * 4);
        CP_ASYNC16(sBl_b + st * BUF + o0, Bl + (long)(bn + ar) * 128 + p + ac * 4);
        CP_ASYNC16(sBl_b + st * BUF + o1, Bl + (long)(bn + 64 + ar) * 128 + p + ac * 4);
    };
    auto issueA1 = [&](int st, int k0) {
        int p = k0 >> 1;
        uint32_t o0 = (uint32_t)((ar * 8 + pc * 4) * 4);
        uint32_t o1 = (uint32_t)(((64 + ar) * 8 + pc * 4) * 4);
        CP_ASYNC16(sAh_b + st * BUF + o0, g_ah + (long)agr0 * 128 + p + ac * 4);
        CP_ASYNC16(sAh_b + st * BUF + o1, g_ah + (long)agr1 * 128 + p + ac * 4);
    };
    auto gloadA0 = [&](int k0) {
        const float* src = x + (long)xrow * 256 + k0;
#pragma unroll
        for (int i = 0; i < 4; i++) *(float4*)&xr[i * 4] = *(const float4*)(src + i * 4);
    };
    auto storeA0 = [&](int st) {
        uint32_t wh[8];
#pragma unroll
        for (int w = 0; w < 8; w++) {
            __half2 p = __floats2half2_rn(xr[2 * w], xr[2 * w + 1]);
            wh[w] = *reinterpret_cast<uint32_t*>(&p);
        }
        *(uint4*)&sAh[st][tid * 8 + swt * 4]       = *(uint4*)&wh[0];
        *(uint4*)&sAh[st][tid * 8 + (swt ^ 1) * 4] = *(uint4*)&wh[4];
    };

    // prologue: tile 0
    if (LAYER == 0) {
        gloadA0(0);
        issueB(0, 0);
        CP_COMMIT();
        storeA0(0);
        gloadA0(16);
    } else {
        issueA1(0, 0);
        issueB(0, 0);
        CP_COMMIT();
    }

#pragma unroll 1
    for (int it = 0; it < 16; it++) {
        int cb = it & 1;
        CP_WAIT0();
        __syncthreads();
        if (it < 15) {
            issueB(cb ^ 1, (it + 1) * 16);
            if (LAYER == 0) {
                CP_COMMIT();
                storeA0(cb ^ 1);           // regs hold tile it+1
                if (it < 14) gloadA0((it + 2) * 16);
            } else {
                issueA1(cb ^ 1, (it + 1) * 16);
                CP_COMMIT();
            }
        }
        // ---- compute tile it ----
        uint32_t ah[4][4];
#pragma unroll
        for (int mi = 0; mi < 4; mi++) {
            uint32_t base = (uint32_t)((wm + mi * 16) * 32);
            ldsm4(ah[mi], sAh_b + cb * BUF + base + lds_offA);
        }
#pragma unroll
        for (int nip = 0; nip < 4; nip++) {
            uint32_t bh[4], bl[4];
            uint32_t base = (uint32_t)((wn + nip * 16) * 32);
            ldsm4(bh, sBh_b + cb * BUF + base + lds_offB);
            ldsm4(bl, sBl_b + cb * BUF + base + lds_offB);
#pragma unroll
            for (int mi = 0; mi < 4; mi++) {
                MMA_F16(acc[mi][2 * nip],     ah[mi], bh[0], bh[1]);
                MMA_F16(acc[mi][2 * nip],     ah[mi], bl[0], bl[1]);
                MMA_F16(acc[mi][2 * nip + 1], ah[mi], bh[2], bh[3]);
                MMA_F16(acc[mi][2 * nip + 1], ah[mi], bl[2], bl[3]);
            }
        }
    }

    // ---- epilogue: fp16 feature store + fused alpha partials ----
    int head = (H == 1) ? 0 : (bn + wn) / (CF / H);  // warp's 64 cols lie in one head (H=4)
#pragma unroll
    for (int mi = 0; mi < 4; mi++) {
        int r = bm + wm + mi * 16 + g;
        float sA = 0, dA = 0, sB = 0, dB = 0;
#pragma unroll
        for (int ni = 0; ni < 8; ni++) {
            int cc = bn + wn + ni * 8 + 2 * t4;
            int wd = cc >> 1;
            float c0 = __ldg(&a_s[cc]), c1 = __ldg(&a_s[cc + 1]);
            float d0 = __ldg(&a_d[cc]), d1 = __ldg(&a_d[cc + 1]);
            sA += acc[mi][ni][0] * c0 + acc[mi][ni][1] * c1;
            dA += acc[mi][ni][0] * d0 + acc[mi][ni][1] * d1;
            sB += acc[mi][ni][2] * c0 + acc[mi][ni][3] * c1;
            dB += acc[mi][ni][2] * d0 + acc[mi][ni][3] * d1;
            if (r < M) {
                __half2 p = __floats2half2_rn(acc[mi][ni][0], acc[mi][ni][1]);
                g_hf16[(long)r * 128 + wd] = *reinterpret_cast<uint32_t*>(&p);
            }
            if (r + 8 < M) {
                __half2 p = __floats2half2_rn(acc[mi][ni][2], acc[mi][ni][3]);
                g_hf16[(long)(r + 8) * 128 + wd] = *reinterpret_cast<uint32_t*>(&p);
            }
        }
        sA += __shfl_xor_sync(0xffffffffu, sA, 1); sA += __shfl_xor_sync(0xffffffffu, sA, 2);
        dA += __shfl_xor_sync(0xffffffffu, dA, 1); dA += __shfl_xor_sync(0xffffffffu, dA, 2);
        sB += __shfl_xor_sync(0xffffffffu, sB, 1); sB += __shfl_xor_sync(0xffffffffu, sB, 2);
        dB += __shfl_xor_sync(0xffffffffu, dB, 1); dB += __shfl_xor_sync(0xffffffffu, dB, 2);
        if (t4 == 0) {
            if (r < M) {
                atomicAdd(&asrc[r * H + head], sA);
                atomicAdd(&adst[r * H + head], dA);
            }
            if (r + 8 < M) {
                atomicAdd(&asrc[(r + 8) * H + head], sB);
                atomicAdd(&adst[(r + 8) * H + head], dB);
            }
        }
    }
}

// ---------------- fused softmax-attention aggregation: warp per dst node ----------------
template <int H, int CH, bool ELU_ACT, bool SPLIT, int LYR>
__global__ void agg_kernel(const float* __restrict__ bias, float* __restrict__ out) {
    int node = blockIdx.x * 8 + (threadIdx.x >> 5);
    if (node >= NN) return;
    int lane = threadIdx.x & 31;
    int head = (lane * 8) / CH;
    const float* asrc = (LYR == 0) ? g_asrc : g_asrc2;
    const float* adstp = (LYR == 0) ? g_adst : g_adst2;
    float ad = adstp[node * H + head];
    const uint4* hb = (const uint4*)g_hf16;
    float a0 = 0, a1 = 0, a2 = 0, a3 = 0, a4 = 0, a5 = 0, a6 = 0, a7 = 0;
    float denom = 0.f;
    int j0 = g_rowptr[node], j1 = g_rowptr[node + 1];

    auto accum = [&](uint4 pk, float w) {
        float2 f0 = __half22float2(*reinterpret_cast<__half2*>(&pk.x));
        float2 f1 = __half22float2(*reinterpret_cast<__half2*>(&pk.y));
        float2 f2 = __half22float2(*reinterpret_cast<__half2*>(&pk.z));
        float2 f3 = __half22float2(*reinterpret_cast<__half2*>(&pk.w));
        a0 += w * f0.x; a1 += w * f0.y; a2 += w * f1.x; a3 += w * f1.y;
        a4 += w * f2.x; a5 += w * f2.y; a6 += w * f3.x; a7 += w * f3.y;
    };
    auto mkw = [&](float e) {
        e += ad;
        e = (e > 0.f) ? e : 0.2f * e;
        return __expf(e);
    };

    int j = j0;
    for (; j + 4 <= j1; j += 4) {
        int s0 = __ldg(&g_colsrc[j]);
        int s1 = __ldg(&g_colsrc[j + 1]);
        int s2 = __ldg(&g_colsrc[j + 2]);
        int s3 = __ldg(&g_colsrc[j + 3]);
        float e0 = __ldg(&asrc[s0 * H + head]);
        float e1 = __ldg(&asrc[s1 * H + head]);
        float e2 = __ldg(&asrc[s2 * H + head]);
        float e3 = __ldg(&asrc[s3 * H + head]);
        uint4 p0 = __ldg(&hb[(long)s0 * 32 + lane]);
        uint4 p1 = __ldg(&hb[(long)s1 * 32 + lane]);
        uint4 p2 = __ldg(&hb[(long)s2 * 32 + lane]);
        uint4 p3 = __ldg(&hb[(long)s3 * 32 + lane]);
        float w0 = mkw(e0), w1 = mkw(e1), w2 = mkw(e2), w3 = mkw(e3);
        denom += (w0 + w1) + (w2 + w3);
        accum(p0, w0); accum(p1, w1); accum(p2, w2); accum(p3, w3);
    }
    for (; j < j1; j++) {
        int s = __ldg(&g_colsrc[j]);
        float w = mkw(__ldg(&asrc[s * H + head]));
        denom += w;
        accum(__ldg(&hb[(long)s * 32 + lane]), w);
    }

    float inv = 1.f / denom;
    const float4* bb = (const float4*)bias + lane * 2;
    float4 b0 = bb[0], b1 = bb[1];
    float r[8];
    r[0] = a0 * inv + b0.x; r[1] = a1 * inv + b0.y;
    r[2] = a2 * inv + b0.z; r[3] = a3 * inv + b0.w;
    r[4] = a4 * inv + b1.x; r[5] = a5 * inv + b1.y;
    r[6] = a6 * inv + b1.z; r[7] = a7 * inv + b1.w;
    if (ELU_ACT) {
#pragma unroll
        for (int k = 0; k < 8; k++) r[k] = (r[k] > 0.f) ? r[k] : expm1f(r[k]);
    }
    if (SPLIT) {
        uint32_t wh[4];
#pragma unroll
        for (int p = 0; p < 4; p++) {
            __half2 h = __floats2half2_rn(r[2 * p], r[2 * p + 1]);
            wh[p] = *reinterpret_cast<uint32_t*>(&h);
        }
        long ob = (long)node * 128 + lane * 4;
        *(uint4*)&g_ah[ob] = *(uint4*)wh;
        if (lane == 0) {   // zero layer-2 alpha slots for gemm2's atomics
            g_asrc2[node] = 0.f;
            g_adst2[node] = 0.f;
        }
    } else {
        long ob = (long)node * CF + lane * 8;
        *(float4*)&out[ob]     = make_float4(r[0], r[1], r[2], r[3]);
        *(float4*)&out[ob + 4] = make_float4(r[4], r[5], r[6], r[7]);
    }
}

// ---------------- launch: kernel launches ONLY (graph-capture safe) ----------------
extern "C" void kernel_launch(void* const* d_in, const int* in_sizes, int n_in,
                              void* d_out, int out_size) {
    const float* x    = (const float*)d_in[0];
    const int* ei32   = (const int*)d_in[1];
    const float* W1   = (const float*)d_in[2];
    const float* as1  = (const float*)d_in[3];
    const float* ad1  = (const float*)d_in[4];
    const float* b1   = (const float*)d_in[5];
    const float* W2   = (const float*)d_in[6];
    const float* as2  = (const float*)d_in[7];
    const float* ad2  = (const float*)d_in[8];
    const float* b2   = (const float*)d_in[9];
    float* out        = (float*)d_out;

    dim3 gg((NN + 127) / 128, 2);

    // order keeps gemm1 in the ncu capture window (position 4)
    zero_all_kernel<<<(NN + 255) / 256, 256>>>();
    split_w_kernel<0><<<(256 * 128 + 255) / 256, 256>>>(W1);
    split_w_kernel<1><<<(256 * 128 + 255) / 256, 256>>>(W2);
    gemmf16_kernel<0, 4><<<gg, 128>>>(NN, x, as1, ad1);

    detect_kernel<<<1, 32>>>(ei32);
    hist_kernel<<<(EETOT + 255) / 256, 256>>>(ei32);
    scan_kernel<<<1, 1024>>>();
    scatter_kernel<<<(EETOT + 255) / 256, 256>>>(ei32);

    agg_kernel<4, 64, true, true, 0><<<(NN + 7) / 8, 256>>>(b1, (float*)0);
    gemmf16_kernel<1, 1><<<gg, 128>>>(NN, (const float*)0, as2, ad2);
    agg_kernel<1, 256, false, false, 1><<<(NN + 7) / 8, 256>>>(b2, out);
}

// round 17
// speedup vs baseline: 1.4069x; 1.0126x over previous
#include <cuda_runtime.h>
#include <cuda_fp16.h>
#include <stdint.h>
#include <math.h>

#define NN 50000
#define EC 800000
#define EETOT 850000
#define CF 256

// ---------------- scratch (static __device__, no allocations) ----------------
__device__ __align__(256) uint32_t g_ah[NN * 128];    // A operand fp16 (packed half2 k-pairs)
__device__ __align__(256) uint32_t g_w1h[256 * 128];  // W packed [n][k-pair] (n-major) hi
__device__ __align__(256) uint32_t g_w1l[256 * 128];  //                                lo
__device__ __align__(256) uint32_t g_w2h[256 * 128];
__device__ __align__(256) uint32_t g_w2l[256 * 128];
__device__ __align__(256) uint32_t g_hf16[NN * 128];  // features, packed half2 (only copy)
__device__ __align__(256) float g_asrc[NN * 4];       // layer-1 alpha partials (atomics)
__device__ __align__(256) float g_adst[NN * 4];
__device__ __align__(256) float g_asrc2[NN];          // layer-2 alpha partials (zeroed by agg1)
__device__ __align__(256) float g_adst2[NN];
__device__ int g_rowptr[NN + 1];
__device__ int g_cnt[NN];
__device__ int g_cur[NN];
__device__ int g_colsrc[EETOT];
__device__ int g_is64;

// ---------------- helpers ----------------
__device__ __forceinline__ uint32_t pack_split_h2(float v0, float v1, uint32_t& lo_out) {
    __half h0 = __float2half_rn(v0);
    __half l0 = __float2half_rn(v0 - __half2float(h0));
    __half h1 = __float2half_rn(v1);
    __half l1 = __float2half_rn(v1 - __half2float(h1));
    __half2 hh = __halves2half2(h0, h1);
    __half2 ll = __halves2half2(l0, l1);
    lo_out = *reinterpret_cast<uint32_t*>(&ll);
    return *reinterpret_cast<uint32_t*>(&hh);
}

#define MMA_F16(c, a, b0, b1)                                                          \
    asm volatile(                                                                      \
        "mma.sync.aligned.m16n8k16.row.col.f32.f16.f16.f32 "                           \
        "{%0,%1,%2,%3},{%4,%5,%6,%7},{%8,%9},{%0,%1,%2,%3};"                           \
        : "+f"(c[0]), "+f"(c[1]), "+f"(c[2]), "+f"(c[3])                               \
        : "r"(a[0]), "r"(a[1]), "r"(a[2]), "r"(a[3]), "r"(b0), "r"(b1))

__device__ __forceinline__ void ldsm4(uint32_t (&r)[4], uint32_t saddr) {
    asm volatile("ldmatrix.sync.aligned.m8n8.x4.shared.b16 {%0,%1,%2,%3}, [%4];"
                 : "=r"(r[0]), "=r"(r[1]), "=r"(r[2]), "=r"(r[3])
                 : "r"(saddr));
}

#define CP_ASYNC16(dst_u32, src_ptr)                                                   \
    asm volatile("cp.async.cg.shared.global [%0], [%1], 16;" ::"r"(dst_u32), "l"(src_ptr))
#define CP_COMMIT() asm volatile("cp.async.commit_group;")
#define CP_WAIT0()  asm volatile("cp.async.wait_group 0;")

__device__ __forceinline__ int edge_at(const int* __restrict__ ei32, long pos, int is64) {
    int v = is64 ? ei32[2 * pos] : ei32[pos];
    v = (v < 0) ? 0 : v;
    return (v >= NN) ? (NN - 1) : v;
}

// ---------------- edge dtype detection (warp-parallel) ----------------
__global__ void detect_kernel(const int* __restrict__ ei32) {
    int lane = threadIdx.x;
    int bad = 0;
    for (int k = lane; k < 64; k += 32)
        if (ei32[2 * k + 1] != 0) bad = 1;
    unsigned m = __ballot_sync(0xffffffffu, bad);
    if (lane == 0) g_is64 = (m == 0);
}

// ---------------- W split: fp16 hi/lo, n-major [n][kp] layout ----------------
template <int L>
__global__ void split_w_kernel(const float* __restrict__ W) {
    uint32_t* wh = (L == 0) ? g_w1h : g_w2h;
    uint32_t* wl = (L == 0) ? g_w1l : g_w2l;
    int i = blockIdx.x * 256 + threadIdx.x;
    if (i >= 256 * 128) return;
    int n = i >> 7, kp = i & 127;
    float v0 = W[(2 * kp) * 256 + n], v1 = W[(2 * kp + 1) * 256 + n];
    uint32_t lo;
    uint32_t hi = pack_split_h2(v0, v1, lo);
    wh[n * 128 + kp] = hi;
    wl[n * 128 + kp] = lo;
}

// ---------------- zero ----------------
__global__ void zero_all_kernel() {
    int i = blockIdx.x * 256 + threadIdx.x;
    if (i < NN) {
        g_cnt[i] = 0;
        g_cur[i] = 0;
        *(float4*)&g_asrc[i * 4] = make_float4(0.f, 0.f, 0.f, 0.f);
        *(float4*)&g_adst[i * 4] = make_float4(0.f, 0.f, 0.f, 0.f);
    }
}

// ---------------- CSR build ----------------
__global__ void hist_kernel(const int* __restrict__ ei32) {
    int i = blockIdx.x * 256 + threadIdx.x;
    if (i >= EETOT) return;
    int is64 = g_is64;
    int dst = (i < EC) ? edge_at(ei32, (long)EC + i, is64) : (i - EC);
    atomicAdd(&g_cnt[dst], 1);
}

__global__ void scan_kernel() {
    __shared__ int s[1024];
    int t = threadIdx.x;
    const int chunk = (NN + 1023) / 1024;
    int lo = t * chunk;
    int hi = lo + chunk; if (hi > NN) hi = NN;
    int sum = 0;
    for (int i = lo; i < hi; i++) sum += g_cnt[i];
    s[t] = sum;
    __syncthreads();
    for (int d = 1; d < 1024; d <<= 1) {
        int v = (t >= d) ? s[t - d] : 0;
        __syncthreads();
        s[t] += v;
        __syncthreads();
    }
    int run = s[t] - sum;
    for (int i = lo; i < hi; i++) { g_rowptr[i] = run; run += g_cnt[i]; }
    if (t == 0) g_rowptr[NN] = EETOT;
}

__global__ void scatter_kernel(const int* __restrict__ ei32) {
    int i = blockIdx.x * 256 + threadIdx.x;
    if (i >= EETOT) return;
    int is64 = g_is64;
    int src, dst;
    if (i < EC) {
        src = edge_at(ei32, i, is64);
        dst = edge_at(ei32, (long)EC + i, is64);
    } else {
        src = i - EC;
        dst = i - EC;
    }
    int pos = g_rowptr[dst] + atomicAdd(&g_cur[dst], 1);
    g_colsrc[pos] = src;
}

// ---------------- GEMM + fused alpha: h = A @ W, 2-product split-fp16 ----------------
// C = Ah*(Bh+Bl). CTA 128x128, 4 warps (2x2), warp tile 64x64, BK=32 (two K16 subs
// per stage -> 8 waits/syncs instead of 16). A+B fragments via ldmatrix.x4.
// Sub-tiles: 128 rows x 8 words, XOR-swizzled 16B chunks. Smem 48KB, 2 CTA/SM.
// LAYER 0: A from fp32 x, converted in-register (32 floats staged). LAYER 1: cp.async.
template <int LAYER, int H>
__global__ void __launch_bounds__(128) gemmf16_kernel(
    int M, const float* __restrict__ x, const float* __restrict__ a_s,
    const float* __restrict__ a_d) {
    const uint32_t* __restrict__ Bh = (LAYER == 0) ? g_w1h : g_w2h;
    const uint32_t* __restrict__ Bl = (LAYER == 0) ? g_w1l : g_w2l;
    float* __restrict__ asrc = (LAYER == 0) ? g_asrc : g_asrc2;
    float* __restrict__ adst = (LAYER == 0) ? g_adst : g_adst2;

    // [stage][sub][128*8 words]
    __shared__ __align__(16) uint32_t sAh[2 * 2 * 1024];
    __shared__ __align__(16) uint32_t sBh[2 * 2 * 1024];
    __shared__ __align__(16) uint32_t sBl[2 * 2 * 1024];

    int tid = threadIdx.x;
    int lane = tid & 31, warp = tid >> 5;
    int g = lane >> 2, t4 = lane & 3;
    int wm = (warp >> 1) * 64, wn = (warp & 1) * 64;
    int bm = blockIdx.x * 128, bn = blockIdx.y * 128;

    float acc[4][8][4] = {};

    int ar = tid >> 1, ac = tid & 1;
    int pc = ac ^ ((ar >> 2) & 1);        // physical chunk (rows ar and 64+ar share it)
    int agr0 = bm + ar;       if (agr0 > M - 1) agr0 = M - 1;
    int agr1 = bm + 64 + ar;  if (agr1 > M - 1) agr1 = M - 1;
    int xrow = bm + tid;      if (xrow > M - 1) xrow = M - 1;
    int swt = (tid >> 2) & 1;

    uint32_t sAh_b = (uint32_t)__cvta_generic_to_shared(&sAh[0]);
    uint32_t sBh_b = (uint32_t)__cvta_generic_to_shared(&sBh[0]);
    uint32_t sBl_b = (uint32_t)__cvta_generic_to_shared(&sBl[0]);
    const uint32_t SUB = 4096, STAGE = 8192;   // bytes

    uint32_t lds_offA =
        (uint32_t)(((lane & 15) * 8 + (((lane >> 4) ^ ((lane >> 2) & 1)) << 2)) * 4);
    uint32_t lds_offB =
        (uint32_t)((((lane >> 4) * 8 + (lane & 7)) * 8 +
                    ((((lane >> 3) & 1) ^ ((lane >> 2) & 1)) << 2)) * 4);

    float xr[32];  // layer-0 raw fp32 row chunk (one BK=32 stage)

    auto issueB = [&](int st, int k0) {
#pragma unroll
        for (int sub = 0; sub < 2; sub++) {
            int p = (k0 >> 1) + sub * 8;
            uint32_t o0 = st * STAGE + sub * SUB + (uint32_t)((ar * 8 + pc * 4) * 4);
            uint32_t o1 = st * STAGE + sub * SUB + (uint32_t)(((64 + ar) * 8 + pc * 4) * 4);
            CP_ASYNC16(sBh_b + o0, Bh + (long)(bn + ar) * 128 + p + ac * 4);
            CP_ASYNC16(sBh_b + o1, Bh + (long)(bn + 64 + ar) * 128 + p + ac * 4);
            CP_ASYNC16(sBl_b + o0, Bl + (long)(bn + ar) * 128 + p + ac * 4);
            CP_ASYNC16(sBl_b + o1, Bl + (long)(bn + 64 + ar) * 128 + p + ac * 4);
        }
    };
    auto issueA1 = [&](int st, int k0) {
#pragma unroll
        for (int sub = 0; sub < 2; sub++) {
            int p = (k0 >> 1) + sub * 8;
            uint32_t o0 = st * STAGE + sub * SUB + (uint32_t)((ar * 8 + pc * 4) * 4);
            uint32_t o1 = st * STAGE + sub * SUB + (uint32_t)(((64 + ar) * 8 + pc * 4) * 4);
            CP_ASYNC16(sAh_b + o0, g_ah + (long)agr0 * 128 + p + ac * 4);
            CP_ASYNC16(sAh_b + o1, g_ah + (long)agr1 * 128 + p + ac * 4);
        }
    };
    auto gloadA0 = [&](int k0) {
        const float* src = x + (long)xrow * 256 + k0;
#pragma unroll
        for (int i = 0; i < 8; i++) *(float4*)&xr[i * 4] = *(const float4*)(src + i * 4);
    };
    auto storeA0 = [&](int st) {
#pragma unroll
        for (int sub = 0; sub < 2; sub++) {
            uint32_t wh[8];
#pragma unroll
            for (int w = 0; w < 8; w++) {
                __half2 p = __floats2half2_rn(xr[sub * 16 + 2 * w], xr[sub * 16 + 2 * w + 1]);
                wh[w] = *reinterpret_cast<uint32_t*>(&p);
            }
            uint32_t* base = &sAh[st * 2048 + sub * 1024 + tid * 8];
            *(uint4*)&base[swt * 4]       = *(uint4*)&wh[0];
            *(uint4*)&base[(swt ^ 1) * 4] = *(uint4*)&wh[4];
        }
    };

    // prologue: stage 0 (K 0..31)
    if (LAYER == 0) {
        gloadA0(0);
        issueB(0, 0);
        CP_COMMIT();
        storeA0(0);
        gloadA0(32);
    } else {
        issueA1(0, 0);
        issueB(0, 0);
        CP_COMMIT();
    }

#pragma unroll 1
    for (int it = 0; it < 8; it++) {
        int cb = it & 1;
        CP_WAIT0();
        __syncthreads();
        if (it < 7) {
            issueB(cb ^ 1, (it + 1) * 32);
            if (LAYER == 0) {
                CP_COMMIT();
                storeA0(cb ^ 1);           // regs hold stage it+1
                if (it < 6) gloadA0((it + 2) * 32);
            } else {
                issueA1(cb ^ 1, (it + 1) * 32);
                CP_COMMIT();
            }
        }
        // ---- compute stage it: two K16 sub-tiles ----
#pragma unroll
        for (int sub = 0; sub < 2; sub++) {
            uint32_t sbase = cb * STAGE + sub * SUB;
            uint32_t ah[4][4];
#pragma unroll
            for (int mi = 0; mi < 4; mi++) {
                uint32_t base = (uint32_t)((wm + mi * 16) * 32);
                ldsm4(ah[mi], sAh_b + sbase + base + lds_offA);
            }
#pragma unroll
            for (int nip = 0; nip < 4; nip++) {
                uint32_t bh[4], bl[4];
                uint32_t base = (uint32_t)((wn + nip * 16) * 32);
                ldsm4(bh, sBh_b + sbase + base + lds_offB);
                ldsm4(bl, sBl_b + sbase + base + lds_offB);
#pragma unroll
                for (int mi = 0; mi < 4; mi++) {
                    MMA_F16(acc[mi][2 * nip],     ah[mi], bh[0], bh[1]);
                    MMA_F16(acc[mi][2 * nip],     ah[mi], bl[0], bl[1]);
                    MMA_F16(acc[mi][2 * nip + 1], ah[mi], bh[2], bh[3]);
                    MMA_F16(acc[mi][2 * nip + 1], ah[mi], bl[2], bl[3]);
                }
            }
        }
    }

    // ---- epilogue: fp16 feature store + fused alpha partials ----
    int head = (H == 1) ? 0 : (bn + wn) / (CF / H);
#pragma unroll
    for (int mi = 0; mi < 4; mi++) {
        int r = bm + wm + mi * 16 + g;
        float sA = 0, dA = 0, sB = 0, dB = 0;
#pragma unroll
        for (int ni = 0; ni < 8; ni++) {
            int cc = bn + wn + ni * 8 + 2 * t4;
            int wd = cc >> 1;
            float c0 = __ldg(&a_s[cc]), c1 = __ldg(&a_s[cc + 1]);
            float d0 = __ldg(&a_d[cc]), d1 = __ldg(&a_d[cc + 1]);
            sA += acc[mi][ni][0] * c0 + acc[mi][ni][1] * c1;
            dA += acc[mi][ni][0] * d0 + acc[mi][ni][1] * d1;
            sB += acc[mi][ni][2] * c0 + acc[mi][ni][3] * c1;
            dB += acc[mi][ni][2] * d0 + acc[mi][ni][3] * d1;
            if (r < M) {
                __half2 p = __floats2half2_rn(acc[mi][ni][0], acc[mi][ni][1]);
                g_hf16[(long)r * 128 + wd] = *reinterpret_cast<uint32_t*>(&p);
            }
            if (r + 8 < M) {
                __half2 p = __floats2half2_rn(acc[mi][ni][2], acc[mi][ni][3]);
                g_hf16[(long)(r + 8) * 128 + wd] = *reinterpret_cast<uint32_t*>(&p);
            }
        }
        sA += __shfl_xor_sync(0xffffffffu, sA, 1); sA += __shfl_xor_sync(0xffffffffu, sA, 2);
        dA += __shfl_xor_sync(0xffffffffu, dA, 1); dA += __shfl_xor_sync(0xffffffffu, dA, 2);
        sB += __shfl_xor_sync(0xffffffffu, sB, 1); sB += __shfl_xor_sync(0xffffffffu, sB, 2);
        dB += __shfl_xor_sync(0xffffffffu, dB, 1); dB += __shfl_xor_sync(0xffffffffu, dB, 2);
        if (t4 == 0) {
            if (r < M) {
                atomicAdd(&asrc[r * H + head], sA);
                atomicAdd(&adst[r * H + head], dA);
            }
            if (r + 8 < M) {
                atomicAdd(&asrc[(r + 8) * H + head], sB);
                atomicAdd(&adst[(r + 8) * H + head], dB);
            }
        }
    }
}

// ---------------- fused softmax-attention aggregation: warp per dst node ----------------
template <int H, int CH, bool ELU_ACT, bool SPLIT, int LYR>
__global__ void agg_kernel(const float* __restrict__ bias, float* __restrict__ out) {
    int node = blockIdx.x * 8 + (threadIdx.x >> 5);
    if (node >= NN) return;
    int lane = threadIdx.x & 31;
    int head = (lane * 8) / CH;
    const float* asrc = (LYR == 0) ? g_asrc : g_asrc2;
    const float* adstp = (LYR == 0) ? g_adst : g_adst2;
    float ad = adstp[node * H + head];
    const uint4* hb = (const uint4*)g_hf16;
    float a0 = 0, a1 = 0, a2 = 0, a3 = 0, a4 = 0, a5 = 0, a6 = 0, a7 = 0;
    float denom = 0.f;
    int j0 = g_rowptr[node], j1 = g_rowptr[node + 1];

    auto accum = [&](uint4 pk, float w) {
        float2 f0 = __half22float2(*reinterpret_cast<__half2*>(&pk.x));
        float2 f1 = __half22float2(*reinterpret_cast<__half2*>(&pk.y));
        float2 f2 = __half22float2(*reinterpret_cast<__half2*>(&pk.z));
        float2 f3 = __half22float2(*reinterpret_cast<__half2*>(&pk.w));
        a0 += w * f0.x; a1 += w * f0.y; a2 += w * f1.x; a3 += w * f1.y;
        a4 += w * f2.x; a5 += w * f2.y; a6 += w * f3.x; a7 += w * f3.y;
    };
    auto mkw = [&](float e) {
        e += ad;
        e = (e > 0.f) ? e : 0.2f * e;
        return __expf(e);
    };

    int j = j0;
    for (; j + 4 <= j1; j += 4) {
        int s0 = __ldg(&g_colsrc[j]);
        int s1 = __ldg(&g_colsrc[j + 1]);
        int s2 = __ldg(&g_colsrc[j + 2]);
        int s3 = __ldg(&g_colsrc[j + 3]);
        float e0 = __ldg(&asrc[s0 * H + head]);
        float e1 = __ldg(&asrc[s1 * H + head]);
        float e2 = __ldg(&asrc[s2 * H + head]);
        float e3 = __ldg(&asrc[s3 * H + head]);
        uint4 p0 = __ldg(&hb[(long)s0 * 32 + lane]);
        uint4 p1 = __ldg(&hb[(long)s1 * 32 + lane]);
        uint4 p2 = __ldg(&hb[(long)s2 * 32 + lane]);
        uint4 p3 = __ldg(&hb[(long)s3 * 32 + lane]);
        float w0 = mkw(e0), w1 = mkw(e1), w2 = mkw(e2), w3 = mkw(e3);
        denom += (w0 + w1) + (w2 + w3);
        accum(p0, w0); accum(p1, w1); accum(p2, w2); accum(p3, w3);
    }
    for (; j < j1; j++) {
        int s = __ldg(&g_colsrc[j]);
        float w = mkw(__ldg(&asrc[s * H + head]));
        denom += w;
        accum(__ldg(&hb[(long)s * 32 + lane]), w);
    }

    float inv = 1.f / denom;
    const float4* bb = (const float4*)bias + lane * 2;
    float4 b0 = bb[0], b1 = bb[1];
    float r[8];
    r[0] = a0 * inv + b0.x; r[1] = a1 * inv + b0.y;
    r[2] = a2 * inv + b0.z; r[3] = a3 * inv + b0.w;
    r[4] = a4 * inv + b1.x; r[5] = a5 * inv + b1.y;
    r[6] = a6 * inv + b1.z; r[7] = a7 * inv + b1.w;
    if (ELU_ACT) {
#pragma unroll
        for (int k = 0; k < 8; k++) r[k] = (r[k] > 0.f) ? r[k] : expm1f(r[k]);
    }
    if (SPLIT) {
        uint32_t wh[4];
#pragma unroll
        for (int p = 0; p < 4; p++) {
            __half2 h = __floats2half2_rn(r[2 * p], r[2 * p + 1]);
            wh[p] = *reinterpret_cast<uint32_t*>(&h);
        }
        long ob = (long)node * 128 + lane * 4;
        *(uint4*)&g_ah[ob] = *(uint4*)wh;
        if (lane == 0) {   // zero layer-2 alpha slots for gemm2's atomics
            g_asrc2[node] = 0.f;
            g_adst2[node] = 0.f;
        }
    } else {
        long ob = (long)node * CF + lane * 8;
        *(float4*)&out[ob]     = make_float4(r[0], r[1], r[2], r[3]);
        *(float4*)&out[ob + 4] = make_float4(r[4], r[5], r[6], r[7]);
    }
}

// ---------------- launch: kernel launches ONLY (graph-capture safe) ----------------
extern "C" void kernel_launch(void* const* d_in, const int* in_sizes, int n_in,
                              void* d_out, int out_size) {
    const float* x    = (const float*)d_in[0];
    const int* ei32   = (const int*)d_in[1];
    const float* W1   = (const float*)d_in[2];
    const float* as1  = (const float*)d_in[3];
    const float* ad1  = (const float*)d_in[4];
    const float* b1   = (const float*)d_in[5];
    const float* W2   = (const float*)d_in[6];
    const float* as2  = (const float*)d_in[7];
    const float* ad2  = (const float*)d_in[8];
    const float* b2   = (const float*)d_in[9];
    float* out        = (float*)d_out;

    dim3 gg((NN + 127) / 128, 2);

    // order keeps gemm1 in the ncu capture window (position 4)
    zero_all_kernel<<<(NN + 255) / 256, 256>>>();
    split_w_kernel<0><<<(256 * 128 + 255) / 256, 256>>>(W1);
    split_w_kernel<1><<<(256 * 128 + 255) / 256, 256>>>(W2);
    gemmf16_kernel<0, 4><<<gg, 128>>>(NN, x, as1, ad1);

    detect_kernel<<<1, 32>>>(ei32);
    hist_kernel<<<(EETOT + 255) / 256, 256>>>(ei32);
    scan_kernel<<<1, 1024>>>();
    scatter_kernel<<<(EETOT + 255) / 256, 256>>>(ei32);

    agg_kernel<4, 64, true, true, 0><<<(NN + 7) / 8, 256>>>(b1, (float*)0);
    gemmf16_kernel<1, 1><<<gg, 128>>>(NN, (const float*)0, as2, ad2);
    agg_kernel<1, 256, false, false, 1><<<(NN + 7) / 8, 256>>>(b2, out);
}